// round 8
// baseline (speedup 1.0000x reference)
#include <cuda_runtime.h>
#include <cstdint>

#define NN 50000
#define EE 1600000
#define ET (EE + NN)
#define DHD 128
#define PERM_SZ (NN + 3 * 128)
#define RB ((NN + 127) / 128)
#define SB ((PERM_SZ + 127) / 128)

#define SA_STRIDE 68
#define OFF_ALO (128 * SA_STRIDE)
#define OFF_B (2 * 128 * SA_STRIDE)
#define GEMM_SMEM ((2 * 128 * SA_STRIDE + 8192) * 4)  // 102400 B

// ---------------- device scratch ----------------
__device__ float g_sX[(size_t)NN * 384];
__device__ float g_bufX[(size_t)NN * 384];
__device__ float g_yH[(size_t)NN * 256];
__device__ float g_bufH[(size_t)NN * 256];
__device__ float g_yHH[(size_t)NN * DHD];
__device__ float g_bufHH[(size_t)NN * DHD];
__device__ float g_z[(size_t)NN * DHD];
__device__ float g_rh[(size_t)NN * DHD];
__device__ float g_WS[18 * DHD * DHD];
__device__ float g_gate[6 * 3 * DHD];
__device__ uint32_t g_imgAggX[384 * 384];
__device__ uint32_t g_imgYH[128 * 256];
__device__ uint32_t g_imgYHH[128 * 128];
__device__ uint32_t g_imgSelfX[3 * 128 * 384];
__device__ uint32_t g_imgSelfH[3 * 128 * 256];
__device__ uint32_t g_imgSelfHH[3 * 128 * 128];
__device__ int g_deg[NN];
__device__ int g_off[NN + 1];
__device__ int g_pos[NN];
__device__ int g_csr[ET];
__device__ int g_cntR[3 * NN];
__device__ int g_roleCnt[3];
__device__ int g_rolePadOff[4];
__device__ int g_rolePos[3];
__device__ int g_perm[PERM_SZ];

// ---------------- tf32 helpers ----------------
__device__ __forceinline__ uint32_t f2tf32(float x) {
    uint32_t r;
    asm("cvt.rna.tf32.f32 %0, %1;" : "=r"(r) : "f"(x));
    return r;
}
__device__ __forceinline__ void split_tf32(float x, uint32_t& hi, uint32_t& lo) {
    asm("cvt.rna.tf32.f32 %0, %1;" : "=r"(hi) : "f"(x));
    float r = x - __uint_as_float(hi);
    asm("cvt.rna.tf32.f32 %0, %1;" : "=r"(lo) : "f"(r));
}
__device__ __forceinline__ void mma8(float* c, const uint32_t* a, uint2 b) {
    asm volatile(
        "mma.sync.aligned.m16n8k8.row.col.f32.tf32.tf32.f32 "
        "{%0,%1,%2,%3},{%4,%5,%6,%7},{%8,%9},{%0,%1,%2,%3};"
        : "+f"(c[0]), "+f"(c[1]), "+f"(c[2]), "+f"(c[3])
        : "r"(a[0]), "r"(a[1]), "r"(a[2]), "r"(a[3]), "r"(b.x), "r"(b.y));
}
__device__ __forceinline__ int fragIdx(int k, int n, int NT) {
    return (((k >> 3) * NT + (n >> 3)) << 6) + (((n & 7) * 4 + (k & 3)) << 1) + ((k >> 2) & 1);
}

// ---------------- preprocessing ----------------
__global__ void init_kernel() {
    int i = blockIdx.x * blockDim.x + threadIdx.x;
    if (i < NN) g_deg[i] = 0;
    if (i < 3 * NN) g_cntR[i] = 0;
    if (i < 3) g_roleCnt[i] = 0;
    if (i < PERM_SZ) g_perm[i] = -1;
}

__global__ void count_kernel(const int* __restrict__ ei, const int* __restrict__ role) {
    int e = blockIdx.x * blockDim.x + threadIdx.x;
    if (e < ET) {
        int srcn, c;
        if (e < EE) { srcn = ei[e]; c = ei[EE + e]; }
        else { srcn = e - EE; c = srcn; }
        atomicAdd(&g_deg[c], 1);
        atomicAdd(&g_cntR[role[srcn] * NN + c], 1);
    }
    if (e < NN) atomicAdd(&g_roleCnt[role[e]], 1);
}

__global__ void scan_kernel() {
    __shared__ int warpsum[32];
    __shared__ int s_tot;
    __shared__ int s_carry;
    int t = threadIdx.x, lane = t & 31, w = t >> 5;
    if (t == 0) s_carry = 0;
    __syncthreads();
    for (int base = 0; base < NN; base += 1024) {
        int v = (base + t < NN) ? g_deg[base + t] : 0;
        int s = v;
#pragma unroll
        for (int o = 1; o < 32; o <<= 1) {
            int n = __shfl_up_sync(~0u, s, o);
            if (lane >= o) s += n;
        }
        if (lane == 31) warpsum[w] = s;
        __syncthreads();
        if (w == 0) {
            int ws = warpsum[lane];
            int t2 = ws;
#pragma unroll
            for (int o = 1; o < 32; o <<= 1) {
                int n = __shfl_up_sync(~0u, t2, o);
                if (lane >= o) t2 += n;
            }
            warpsum[lane] = t2 - ws;
            if (lane == 31) s_tot = t2;
        }
        __syncthreads();
        int excl = s_carry + warpsum[w] + s - v;
        if (base + t < NN) {
            g_off[base + t] = excl;
            g_pos[base + t] = excl;
        }
        __syncthreads();
        if (t == 0) s_carry += s_tot;
        __syncthreads();
    }
    if (t == 0) {
        g_off[NN] = s_carry;
        int o = 0;
        for (int r2 = 0; r2 < 3; r2++) {
            g_rolePadOff[r2] = o;
            g_rolePos[r2] = o;
            o += ((g_roleCnt[r2] + 127) >> 7) << 7;
        }
        g_rolePadOff[3] = o;
    }
}

__global__ void fill_kernel(const int* __restrict__ ei, const int* __restrict__ role) {
    int e = blockIdx.x * blockDim.x + threadIdx.x;
    if (e < ET) {
        int srcn, c;
        if (e < EE) { srcn = ei[e]; c = ei[EE + e]; }
        else { srcn = e - EE; c = srcn; }
        int p = atomicAdd(&g_pos[c], 1);
        g_csr[p] = srcn | (role[srcn] << 28);
    }
    if (e < NN) {
        int q = atomicAdd(&g_rolePos[role[e]], 1);
        g_perm[q] = e;
    }
}

__global__ void gates_kernel(const float* g0, const float* b0, const float* g1, const float* b1,
                             const float* g2, const float* b2, const float* g3, const float* b3,
                             const float* g4, const float* b4, const float* g5, const float* b5) {
    int c = blockIdx.x, t = threadIdx.x;
    const float* gp;
    const float* bp;
    switch (c) {
        case 0: gp = g0; bp = b0; break;
        case 1: gp = g1; bp = b1; break;
        case 2: gp = g2; bp = b2; break;
        case 3: gp = g3; bp = b3; break;
        case 4: gp = g4; bp = b4; break;
        default: gp = g5; bp = b5; break;
    }
    float v = gp[t] + bp[t];
    g_gate[c * 384 + t] = 1.0f / (1.0f + __expf(-v));
}

__global__ void __launch_bounds__(256) ws_all_kernel(
    const float* W0, const float* S0, const float* W1, const float* S1,
    const float* W2, const float* S2, const float* W3, const float* S3,
    const float* W4, const float* S4, const float* W5, const float* S5) {
    int conv = blockIdx.z, r = blockIdx.y, ct = blockIdx.x;
    const float* W;
    const float* S;
    switch (conv) {
        case 0: W = W0; S = S0; break;
        case 1: W = W1; S = S1; break;
        case 2: W = W2; S = S2; break;
        case 3: W = W3; S = S3; break;
        case 4: W = W4; S = S4; break;
        default: W = W5; S = S5; break;
    }
    const float* B = S + ((size_t)r << 14) + ct * 32;
    float* C = g_WS + (((size_t)conv * 3 + r) << 14) + ct * 32;

    __shared__ float As[DHD][33];
    __shared__ float Bs[32][33];
    int tid = threadIdx.x;
    int tr = tid >> 4, tc = tid & 15;
    float acc[8][2] = {};
    for (int kc = 0; kc < DHD; kc += 32) {
#pragma unroll
        for (int t = 0; t < 4; t++) {
            int idx = tid + t * 256;
            int row = idx >> 3;
            int kq = (idx & 7) << 2;
            float4 v = *(const float4*)&W[(size_t)row * DHD + kc + kq];
            As[row][kq] = v.x; As[row][kq + 1] = v.y; As[row][kq + 2] = v.z; As[row][kq + 3] = v.w;
        }
#pragma unroll
        for (int t = 0; t < 4; t++) {
            int idx = tid + t * 256;
            int kk = idx >> 5;
            int j = idx & 31;
            Bs[kk][j] = B[(size_t)(kc + kk) * DHD + j];
        }
        __syncthreads();
#pragma unroll 8
        for (int kk = 0; kk < 32; kk++) {
            float b0 = Bs[kk][tc * 2], b1 = Bs[kk][tc * 2 + 1];
#pragma unroll
            for (int i = 0; i < 8; i++) {
                float a = As[tr * 8 + i][kk];
                acc[i][0] += a * b0;
                acc[i][1] += a * b1;
            }
        }
        __syncthreads();
    }
#pragma unroll
    for (int i = 0; i < 8; i++) {
        C[(size_t)(tr * 8 + i) * DHD + tc * 2] = acc[i][0];
        C[(size_t)(tr * 8 + i) * DHD + tc * 2 + 1] = acc[i][1];
    }
}

__global__ void __launch_bounds__(256) images_kernel(const float* Wxz, const float* Whz,
                                                     const float* Wxr, const float* Whr,
                                                     const float* Wxh, const float* Whh) {
    int fam = blockIdx.y;
    int start = blockIdx.x * 256 + threadIdx.x;
    const int STRIDE = 144 * 256;
    switch (fam) {
        case 0:
            for (int w = start; w < 384 * 384; w += STRIDE) {
                int k = w / 384, n = w % 384;
                int r = k >> 7, kk = k & 127, c = n >> 7, nn = n & 127;
                const float* W = (c == 0) ? Wxz : ((c == 1) ? Wxr : Wxh);
                float val = W[kk * DHD + nn] * g_gate[(c * 2) * 384 + r * 128 + nn];
                g_imgAggX[fragIdx(k, n, 48)] = f2tf32(val);
            }
            break;
        case 1:
            for (int w = start; w < 128 * 256; w += STRIDE) {
                int k = w >> 8, n = w & 255;
                int c = n >> 7, nn = n & 127;
                const float* W = c ? Whr : Whz;
                g_imgYH[fragIdx(k, n, 32)] = f2tf32(W[k * DHD + nn]);
            }
            break;
        case 2:
            for (int w = start; w < 128 * 128; w += STRIDE) {
                int k = w >> 7, n = w & 127;
                g_imgYHH[fragIdx(k, n, 16)] = f2tf32(Whh[k * DHD + n]);
            }
            break;
        case 3:
            for (int w = start; w < 3 * 128 * 384; w += STRIDE) {
                int r = w / 49152, w2 = w % 49152;
                int k = w2 / 384, n = w2 % 384;
                int c = n >> 7, nn = n & 127;
                float val = g_WS[(size_t)((c * 2) * 3 + r) * 16384 + k * DHD + nn];
                g_imgSelfX[r * 49152 + fragIdx(k, n, 48)] = f2tf32(val);
            }
            break;
        case 4:
            for (int w = start; w < 3 * 128 * 256; w += STRIDE) {
                int r = w >> 15, w2 = w & 32767;
                int k = w2 >> 8, n = w2 & 255;
                int c = n >> 7, nn = n & 127;
                float val = g_WS[(size_t)((1 + c * 2) * 3 + r) * 16384 + k * DHD + nn];
                g_imgSelfH[r * 32768 + fragIdx(k, n, 32)] = f2tf32(val);
            }
            break;
        default:
            for (int w = start; w < 3 * 128 * 128; w += STRIDE) {
                int r = w >> 14, w2 = w & 16383;
                int k = w2 >> 7, n = w2 & 127;
                float val = g_WS[(size_t)(5 * 3 + r) * 16384 + k * DHD + n];
                g_imgSelfHH[r * 16384 + fragIdx(k, n, 16)] = f2tf32(val);
            }
            break;
    }
}

// ---------------- shared tf32 GEMM mainloop ----------------
template <int KCH>
__device__ __forceinline__ void mainloop(float (*acc)[8][4], uint32_t* sm,
                                         const float* __restrict__ Xp, int rowStride,
                                         const int* rows, const uint32_t* __restrict__ Bimg,
                                         int NT, int ct, int tid) {
    int lane = tid & 31, wid = tid >> 5;
    int warp_m = wid & 3, warp_n = wid >> 2;
    uint32_t* sAhi = sm;
    uint32_t* sAlo = sm + OFF_ALO;
    uint32_t* sB = sm + OFF_B;

#pragma unroll
    for (int kc = 0; kc < KCH; kc++) {
        if (kc) __syncthreads();
#pragma unroll
        for (int it = 0; it < 8; it++) {
            int i = tid + it * 256;
            int row = i >> 4, f4 = i & 15;
            int gr = rows[row];
            float4 v = make_float4(0.f, 0.f, 0.f, 0.f);
            if (gr >= 0) v = *(const float4*)(Xp + (size_t)gr * rowStride + kc * 64 + f4 * 4);
            int base = row * SA_STRIDE + f4 * 4;
            uint32_t h0, l0, h1, l1, h2, l2, h3, l3;
            split_tf32(v.x, h0, l0);
            split_tf32(v.y, h1, l1);
            split_tf32(v.z, h2, l2);
            split_tf32(v.w, h3, l3);
            *(uint4*)(sAhi + base) = make_uint4(h0, h1, h2, h3);
            *(uint4*)(sAlo + base) = make_uint4(l0, l1, l2, l3);
        }
        const uint32_t* bs = Bimg + ((size_t)(kc * 8) * NT + ct * 16) * 64;
#pragma unroll
        for (int it = 0; it < 8; it++) {
            int i = tid + it * 256;
            int kit = i >> 8, w4 = i & 255;
            ((uint4*)sB)[i] = ((const uint4*)(bs + (size_t)kit * NT * 64))[w4];
        }
        __syncthreads();

#pragma unroll
        for (int kit = 0; kit < 8; kit++) {
            uint32_t ah[2][4], al[2][4];
#pragma unroll
            for (int mt = 0; mt < 2; mt++) {
                int r0 = warp_m * 32 + mt * 16 + (lane >> 2);
                int kk = kit * 8 + (lane & 3);
                ah[mt][0] = sAhi[r0 * SA_STRIDE + kk];
                ah[mt][1] = sAhi[(r0 + 8) * SA_STRIDE + kk];
                ah[mt][2] = sAhi[r0 * SA_STRIDE + kk + 4];
                ah[mt][3] = sAhi[(r0 + 8) * SA_STRIDE + kk + 4];
                al[mt][0] = sAlo[r0 * SA_STRIDE + kk];
                al[mt][1] = sAlo[(r0 + 8) * SA_STRIDE + kk];
                al[mt][2] = sAlo[r0 * SA_STRIDE + kk + 4];
                al[mt][3] = sAlo[(r0 + 8) * SA_STRIDE + kk + 4];
            }
#pragma unroll
            for (int nt = 0; nt < 8; nt++) {
                int gnt = warp_n * 8 + nt;
                uint2 b = *(uint2*)(sB + (kit * 16 + gnt) * 64 + lane * 2);
#pragma unroll
                for (int mt = 0; mt < 2; mt++) {
                    mma8(acc[mt][nt], ah[mt], b);
                    mma8(acc[mt][nt], al[mt], b);
                }
            }
        }
    }
}

// ---------------- aggX ----------------
__global__ void __launch_bounds__(256) gemm_aggX(const float* __restrict__ bxz,
                                                 const float* __restrict__ bxr,
                                                 const float* __restrict__ bxh) {
    extern __shared__ __align__(16) uint32_t sm[];
    __shared__ int rows[128];
    __shared__ float bias[3][128];
    __shared__ float invd[128], cr0[128], cr1[128], cr2[128];
    int tid = threadIdx.x;
    int r0 = blockIdx.x * 128, ct = blockIdx.y;
    const float* bsrc = (ct == 0) ? bxz : ((ct == 1) ? bxr : bxh);
    for (int t = tid; t < 384; t += 256) bias[t >> 7][t & 127] = bsrc[t];
    if (tid < 128) {
        int gr = r0 + tid;
        if (gr < NN) {
            rows[tid] = gr;
            invd[tid] = 1.0f / (float)(g_off[gr + 1] - g_off[gr]);
            cr0[tid] = (float)g_cntR[gr];
            cr1[tid] = (float)g_cntR[NN + gr];
            cr2[tid] = (float)g_cntR[2 * NN + gr];
        } else {
            rows[tid] = -1;
            invd[tid] = 0.f;
            cr0[tid] = cr1[tid] = cr2[tid] = 0.f;
        }
    }
    __syncthreads();
    float acc[2][8][4];
#pragma unroll
    for (int a = 0; a < 2; a++)
#pragma unroll
        for (int b = 0; b < 8; b++)
#pragma unroll
            for (int c = 0; c < 4; c++) acc[a][b][c] = 0.f;
    mainloop<6>(acc, sm, g_sX, 384, rows, g_imgAggX, 48, ct, tid);

    int lane = tid & 31, wid = tid >> 5;
    int warp_m = wid & 3, warp_n = wid >> 2;
#pragma unroll
    for (int mt = 0; mt < 2; mt++) {
#pragma unroll
        for (int h = 0; h < 2; h++) {
            int lrow = warp_m * 32 + mt * 16 + (lane >> 2) + h * 8;
            int grow = r0 + lrow;
            if (grow >= NN) continue;
            float iv = invd[lrow], c0 = cr0[lrow], c1 = cr1[lrow], c2 = cr2[lrow];
            float* op = g_bufX + (size_t)grow * 384 + ct * 128;
#pragma unroll
            for (int nt = 0; nt < 8; nt++) {
                int col = warp_n * 64 + nt * 8 + (lane & 3) * 2;
                float v0 = acc[mt][nt][h * 2] + c0 * bias[0][col] + c1 * bias[1][col] +
                           c2 * bias[2][col];
                float v1 = acc[mt][nt][h * 2 + 1] + c0 * bias[0][col + 1] +
                           c1 * bias[1][col + 1] + c2 * bias[2][col + 1];
                *(float2*)(op + col) = make_float2(v0 * iv, v1 * iv);
            }
        }
    }
}

// ---------------- yH / yHH ----------------
__global__ void __launch_bounds__(256) gemm_yH(const float* __restrict__ H,
                                               const int* __restrict__ role) {
    extern __shared__ __align__(16) uint32_t sm[];
    __shared__ int rows[128];
    __shared__ int role_s[128];
    int tid = threadIdx.x;
    int r0 = blockIdx.x * 128, ct = blockIdx.y;
    int conv = 1 + ct * 2;
    if (tid < 128) {
        int gr = r0 + tid;
        rows[tid] = (gr < NN) ? gr : -1;
        role_s[tid] = (gr < NN) ? role[gr] : 0;
    }
    __syncthreads();
    float acc[2][8][4];
#pragma unroll
    for (int a = 0; a < 2; a++)
#pragma unroll
        for (int b = 0; b < 8; b++)
#pragma unroll
            for (int c = 0; c < 4; c++) acc[a][b][c] = 0.f;
    mainloop<2>(acc, sm, H, 128, rows, g_imgYH, 32, ct, tid);

    int lane = tid & 31, wid = tid >> 5;
    int warp_m = wid & 3, warp_n = wid >> 2;
#pragma unroll
    for (int mt = 0; mt < 2; mt++) {
#pragma unroll
        for (int h = 0; h < 2; h++) {
            int lrow = warp_m * 32 + mt * 16 + (lane >> 2) + h * 8;
            int grow = r0 + lrow;
            if (grow >= NN) continue;
            const float* gp = g_gate + conv * 384 + role_s[lrow] * 128;
            float* yp = g_yH + (size_t)grow * 256 + ct * 128;
#pragma unroll
            for (int nt = 0; nt < 8; nt++) {
                int col = warp_n * 64 + nt * 8 + (lane & 3) * 2;
                *(float2*)(yp + col) = make_float2(acc[mt][nt][h * 2] * gp[col],
                                                   acc[mt][nt][h * 2 + 1] * gp[col + 1]);
            }
        }
    }
}

__global__ void __launch_bounds__(256) gemm_yHH(const int* __restrict__ role) {
    extern __shared__ __align__(16) uint32_t sm[];
    __shared__ int rows[128];
    __shared__ int role_s[128];
    int tid = threadIdx.x;
    int r0 = blockIdx.x * 128;
    if (tid < 128) {
        int gr = r0 + tid;
        rows[tid] = (gr < NN) ? gr : -1;
        role_s[tid] = (gr < NN) ? role[gr] : 0;
    }
    __syncthreads();
    float acc[2][8][4];
#pragma unroll
    for (int a = 0; a < 2; a++)
#pragma unroll
        for (int b = 0; b < 8; b++)
#pragma unroll
            for (int c = 0; c < 4; c++) acc[a][b][c] = 0.f;
    mainloop<2>(acc, sm, g_rh, 128, rows, g_imgYHH, 16, 0, tid);

    int lane = tid & 31, wid = tid >> 5;
    int warp_m = wid & 3, warp_n = wid >> 2;
#pragma unroll
    for (int mt = 0; mt < 2; mt++) {
#pragma unroll
        for (int h = 0; h < 2; h++) {
            int lrow = warp_m * 32 + mt * 16 + (lane >> 2) + h * 8;
            int grow = r0 + lrow;
            if (grow >= NN) continue;
            const float* gp = g_gate + 5 * 384 + role_s[lrow] * 128;
            float* yp = g_yHH + (size_t)grow * 128;
#pragma unroll
            for (int nt = 0; nt < 8; nt++) {
                int col = warp_n * 64 + nt * 8 + (lane & 3) * 2;
                *(float2*)(yp + col) = make_float2(acc[mt][nt][h * 2] * gp[col],
                                                   acc[mt][nt][h * 2 + 1] * gp[col + 1]);
            }
        }
    }
}

// ---------------- self GEMMs ----------------
__global__ void __launch_bounds__(256) gemm_self(const float* __restrict__ Aext, int mode) {
    int rowBase = blockIdx.x * 128;
    if (rowBase >= g_rolePadOff[3]) return;
    extern __shared__ __align__(16) uint32_t sm[];
    __shared__ int rows[128];
    int tid = threadIdx.x, ct = blockIdx.y;

    int r = 0;
    if (rowBase >= g_rolePadOff[1]) r = 1;
    if (rowBase >= g_rolePadOff[2]) r = 2;

    const float* A = Aext ? Aext : g_rh;
    const uint32_t* img;
    int NT, ostride;
    float* obase;
    if (mode == 0) { img = g_imgSelfX + r * 49152; NT = 48; ostride = 384; obase = g_bufX; }
    else if (mode == 1) { img = g_imgSelfH + r * 32768; NT = 32; ostride = 256; obase = g_bufH; }
    else { img = g_imgSelfHH + r * 16384; NT = 16; ostride = 128; obase = g_bufHH; }

    if (tid < 128) rows[tid] = (rowBase + tid < PERM_SZ) ? g_perm[rowBase + tid] : -1;
    __syncthreads();
    float acc[2][8][4];
#pragma unroll
    for (int a = 0; a < 2; a++)
#pragma unroll
        for (int b = 0; b < 8; b++)
#pragma unroll
            for (int c = 0; c < 4; c++) acc[a][b][c] = 0.f;
    mainloop<2>(acc, sm, A, 128, rows, img, NT, ct, tid);

    int lane = tid & 31, wid = tid >> 5;
    int warp_m = wid & 3, warp_n = wid >> 2;
#pragma unroll
    for (int mt = 0; mt < 2; mt++) {
#pragma unroll
        for (int h = 0; h < 2; h++) {
            int lrow = warp_m * 32 + mt * 16 + (lane >> 2) + h * 8;
            int node = rows[lrow];
            if (node < 0) continue;
            float* cp = obase + (size_t)node * ostride + ct * 128;
#pragma unroll
            for (int nt = 0; nt < 8; nt++) {
                int col = warp_n * 64 + nt * 8 + (lane & 3) * 2;
                float2 o = *(float2*)(cp + col);
                o.x += acc[mt][nt][h * 2];
                o.y += acc[mt][nt][h * 2 + 1];
                *(float2*)(cp + col) = o;
            }
        }
    }
}

// ---------------- gathers ----------------
__device__ __forceinline__ void f4add(float4& a, float4 v) {
    a.x += v.x; a.y += v.y; a.z += v.z; a.w += v.w;
}

__global__ void __launch_bounds__(256) spmmX_kernel(const float* __restrict__ X) {
    int w = (blockIdx.x * blockDim.x + threadIdx.x) >> 5;
    int lane = threadIdx.x & 31;
    if (w >= NN) return;
    int s = g_off[w], e = g_off[w + 1];
    float4 a0 = make_float4(0, 0, 0, 0), a1 = a0, a2 = a0;
    int p = s;
    for (; p + 2 <= e; p += 2) {
        int pk0 = g_csr[p], pk1 = g_csr[p + 1];
        float4 v0 = *(const float4*)(X + (size_t)(pk0 & 0x0FFFFFFF) * DHD + (lane << 2));
        float4 v1 = *(const float4*)(X + (size_t)(pk1 & 0x0FFFFFFF) * DHD + (lane << 2));
        int r0v = pk0 >> 28, r1v = pk1 >> 28;
        if (r0v == 0) f4add(a0, v0); else if (r0v == 1) f4add(a1, v0); else f4add(a2, v0);
        if (r1v == 0) f4add(a0, v1); else if (r1v == 1) f4add(a1, v1); else f4add(a2, v1);
    }
    if (p < e) {
        int pk0 = g_csr[p];
        float4 v0 = *(const float4*)(X + (size_t)(pk0 & 0x0FFFFFFF) * DHD + (lane << 2));
        int r0v = pk0 >> 28;
        if (r0v == 0) f4add(a0, v0); else if (r0v == 1) f4add(a1, v0); else f4add(a2, v0);
    }
    float* o = g_sX + (size_t)w * 384 + (lane << 2);
    *(float4*)(o) = a0;
    *(float4*)(o + 128) = a1;
    *(float4*)(o + 256) = a2;
}

__global__ void __launch_bounds__(256) spmmH_kernel() {
    int w = (blockIdx.x * blockDim.x + threadIdx.x) >> 5;
    int lane = threadIdx.x & 31;
    if (w >= NN) return;
    int s = g_off[w], e = g_off[w + 1];
    float4 a0 = make_float4(0, 0, 0, 0), a1 = a0;
    int p = s;
    for (; p + 2 <= e; p += 2) {
        int s0 = g_csr[p] & 0x0FFFFFFF, s1 = g_csr[p + 1] & 0x0FFFFFFF;
        const float* b0 = g_yH + (size_t)s0 * 256 + (lane << 2);
        const float* b1 = g_yH + (size_t)s1 * 256 + (lane << 2);
        float4 u0 = *(const float4*)b0;
        float4 u1 = *(const float4*)(b0 + 128);
        float4 u2 = *(const float4*)b1;
        float4 u3 = *(const float4*)(b1 + 128);
        f4add(a0, u0); f4add(a1, u1); f4add(a0, u2); f4add(a1, u3);
    }
    if (p < e) {
        int s0 = g_csr[p] & 0x0FFFFFFF;
        const float* b0 = g_yH + (size_t)s0 * 256 + (lane << 2);
        f4add(a0, *(const float4*)b0);
        f4add(a1, *(const float4*)(b0 + 128));
    }
    float inv = 1.0f / (float)(e - s);
    float* o = g_bufH + (size_t)w * 256 + (lane << 2);
    *(float4*)o = make_float4(a0.x * inv, a0.y * inv, a0.z * inv, a0.w * inv);
    *(float4*)(o + 128) = make_float4(a1.x * inv, a1.y * inv, a1.z * inv, a1.w * inv);
}

__global__ void __launch_bounds__(256) spmmRH_kernel() {
    int w = (blockIdx.x * blockDim.x + threadIdx.x) >> 5;
    int lane = threadIdx.x & 31;
    if (w >= NN) return;
    int s = g_off[w], e = g_off[w + 1];
    float4 a0 = make_float4(0, 0, 0, 0), a1 = a0;
    int p = s;
    for (; p + 2 <= e; p += 2) {
        int s0 = g_csr[p] & 0x0FFFFFFF, s1 = g_csr[p + 1] & 0x0FFFFFFF;
        f4add(a0, *(const float4*)(g_yHH + (size_t)s0 * DHD + (lane << 2)));
        f4add(a1, *(const float4*)(g_yHH + (size_t)s1 * DHD + (lane << 2)));
    }
    if (p < e) {
        int s0 = g_csr[p] & 0x0FFFFFFF;
        f4add(a0, *(const float4*)(g_yHH + (size_t)s0 * DHD + (lane << 2)));
    }
    float inv = 1.0f / (float)(e - s);
    *(float4*)(g_bufHH + (size_t)w * DHD + (lane << 2)) =
        make_float4((a0.x + a1.x) * inv, (a0.y + a1.y) * inv, (a0.z + a1.z) * inv,
                    (a0.w + a1.w) * inv);
}

// ---------------- combines ----------------
__device__ __forceinline__ float sigm(float x) { return 1.0f / (1.0f + __expf(-x)); }
__device__ __forceinline__ float rl(float x) { return fmaxf(x, 0.f); }

__global__ void combine_zr_kernel(const float* __restrict__ h) {
    size_t idx = (size_t)blockIdx.x * blockDim.x + threadIdx.x;
    if (idx >= (size_t)NN * 32) return;
    size_t i = idx >> 5;
    int q = (int)(idx & 31);
    float4 xz = *(const float4*)(g_bufX + i * 384 + q * 4);
    float4 xr = *(const float4*)(g_bufX + i * 384 + 128 + q * 4);
    float4 hz = *(const float4*)(g_bufH + i * 256 + q * 4);
    float4 hr = *(const float4*)(g_bufH + i * 256 + 128 + q * 4);
    float4 hv = *(const float4*)(h + i * 128 + q * 4);
    float4 z, rr;
    z.x = sigm(rl(xz.x) + rl(hz.x)); z.y = sigm(rl(xz.y) + rl(hz.y));
    z.z = sigm(rl(xz.z) + rl(hz.z)); z.w = sigm(rl(xz.w) + rl(hz.w));
    rr.x = sigm(rl(xr.x) + rl(hr.x)) * hv.x; rr.y = sigm(rl(xr.y) + rl(hr.y)) * hv.y;
    rr.z = sigm(rl(xr.z) + rl(hr.z)) * hv.z; rr.w = sigm(rl(xr.w) + rl(hr.w)) * hv.w;
    *(float4*)(g_z + i * 128 + q * 4) = z;
    *(float4*)(g_rh + i * 128 + q * 4) = rr;
}

__global__ void combine_h_kernel(const float* __restrict__ h, float* __restrict__ out) {
    size_t idx = (size_t)blockIdx.x * blockDim.x + threadIdx.x;
    if (idx >= (size_t)NN * 32) return;
    size_t i = idx >> 5;
    int q = (int)(idx & 31);
    float4 xh = *(const float4*)(g_bufX + i * 384 + 256 + q * 4);
    float4 hh = *(const float4*)(g_bufHH + i * 128 + q * 4);
    float4 zv = *(const float4*)(g_z + i * 128 + q * 4);
    float4 hv = *(const float4*)(h + i * 128 + q * 4);
    float4 o;
    float t;
    t = tanhf(rl(xh.x) + rl(hh.x)); o.x = zv.x * hv.x + (1.f - zv.x) * t;
    t = tanhf(rl(xh.y) + rl(hh.y)); o.y = zv.y * hv.y + (1.f - zv.y) * t;
    t = tanhf(rl(xh.z) + rl(hh.z)); o.z = zv.z * hv.z + (1.f - zv.z) * t;
    t = tanhf(rl(xh.w) + rl(hh.w)); o.w = zv.w * hv.w + (1.f - zv.w) * t;
    *(float4*)(out + i * 128 + q * 4) = o;
}

// ---------------- host launch ----------------
extern "C" void kernel_launch(void* const* d_in, const int* in_sizes, int n_in,
                              void* d_out, int out_size) {
    cudaFuncSetAttribute(gemm_aggX, cudaFuncAttributeMaxDynamicSharedMemorySize, GEMM_SMEM);
    cudaFuncSetAttribute(gemm_yH, cudaFuncAttributeMaxDynamicSharedMemorySize, GEMM_SMEM);
    cudaFuncSetAttribute(gemm_yHH, cudaFuncAttributeMaxDynamicSharedMemorySize, GEMM_SMEM);
    cudaFuncSetAttribute(gemm_self, cudaFuncAttributeMaxDynamicSharedMemorySize, GEMM_SMEM);

    int iEdge = 2, iH = 1;
    if (in_sizes[1] == 2 * EE) { iEdge = 1; iH = 2; }
    const float* x = (const float*)d_in[0];
    const float* h_prev = (const float*)d_in[iH];
    const int* ei = (const int*)d_in[iEdge];
    const int* role = (const int*)d_in[3];

    const float* P[27];
    for (int i = 0; i < 27 && (4 + i) < n_in; i++) P[i] = (const float*)d_in[4 + i];
    float* out = (float*)d_out;

    int spmmGrid = (NN * 32 + 255) / 256;

    init_kernel<<<(3 * NN + 255) / 256, 256>>>();
    count_kernel<<<(ET + 255) / 256, 256>>>(ei, role);
    scan_kernel<<<1, 1024>>>();
    fill_kernel<<<(ET + 255) / 256, 256>>>(ei, role);
    gates_kernel<<<6, 384>>>(P[1], P[2], P[6], P[7], P[10], P[11], P[15], P[16], P[19], P[20],
                             P[24], P[25]);
    ws_all_kernel<<<dim3(4, 3, 6), 256>>>(P[0], P[3], P[5], P[8], P[9], P[12], P[14], P[17],
                                          P[18], P[21], P[23], P[26]);
    images_kernel<<<dim3(144, 6), 256>>>(P[0], P[5], P[9], P[14], P[18], P[23]);

    gemm_yH<<<dim3(RB, 2), 256, GEMM_SMEM>>>(h_prev, role);
    spmmX_kernel<<<spmmGrid, 256>>>(x);
    spmmH_kernel<<<spmmGrid, 256>>>();
    gemm_aggX<<<dim3(RB, 3), 256, GEMM_SMEM>>>(P[4], P[13], P[22]);
    gemm_self<<<dim3(SB, 3), 256, GEMM_SMEM>>>(x, 0);
    gemm_self<<<dim3(SB, 2), 256, GEMM_SMEM>>>(h_prev, 1);
    combine_zr_kernel<<<spmmGrid, 256>>>(h_prev);
    gemm_yHH<<<dim3(RB, 1), 256, GEMM_SMEM>>>(role);
    spmmRH_kernel<<<spmmGrid, 256>>>();
    gemm_self<<<dim3(SB, 1), 256, GEMM_SMEM>>>(nullptr, 2);
    combine_h_kernel<<<spmmGrid, 256>>>(h_prev, out);
}

// round 9
// speedup vs baseline: 1.2541x; 1.2541x over previous
#include <cuda_runtime.h>
#include <cuda_bf16.h>
#include <cstdint>

// Problem constants
#define NN 50000
#define EE 1600000
#define ET (EE + NN)
#define DHD 128
#define PERM_SZ (NN + 3 * 128)
#define GEMM_BLKS ((NN + 127) / 128)       // 391
#define SELF_BLKS ((PERM_SZ + 127) / 128)  // 396

// Dynamic smem (floats): Ahi[128][68] | Alo[128][68] | Bfrag chunk [8][16][64]
#define SA_STRIDE 68
#define OFF_AHI 0
#define OFF_ALO (128 * SA_STRIDE)
#define OFF_B (2 * 128 * SA_STRIDE)
#define GEMM_SMEM ((2 * 128 * SA_STRIDE + 8 * 16 * 64) * 4)  // 102400 B

// ---------------- device scratch ----------------
__device__ __nv_bfloat16 g_y[(size_t)NN * DHD];  // gated message Y in bf16 (halves gather bytes)
__device__ float g_bufA[(size_t)NN * DHD];
__device__ float g_bufB[(size_t)NN * DHD];
__device__ float g_z[(size_t)NN * DHD];
__device__ float g_rh[(size_t)NN * DHD];
__device__ float g_WS[18 * DHD * DHD];       // per-conv per-role W@S (plain [k][n])
__device__ uint32_t g_Bimg[24 * DHD * DHD];  // tf32 fragment-ordered B images
__device__ int g_deg[NN];
__device__ int g_off[NN + 1];
__device__ int g_pos[NN];
__device__ int g_csr[ET];
__device__ int g_roleCnt[3];
__device__ int g_rolePadOff[4];
__device__ int g_rolePos[3];
__device__ int g_perm[PERM_SZ];

// ---------------- tf32 helpers ----------------
__device__ __forceinline__ uint32_t f2tf32(float x) {
    uint32_t r;
    asm("cvt.rna.tf32.f32 %0, %1;" : "=r"(r) : "f"(x));
    return r;
}
__device__ __forceinline__ void split_tf32(float x, uint32_t& hi, uint32_t& lo) {
    asm("cvt.rna.tf32.f32 %0, %1;" : "=r"(hi) : "f"(x));
    float r = x - __uint_as_float(hi);
    asm("cvt.rna.tf32.f32 %0, %1;" : "=r"(lo) : "f"(r));
}
__device__ __forceinline__ void mma8(float* c, const uint32_t* a, uint2 b) {
    asm volatile(
        "mma.sync.aligned.m16n8k8.row.col.f32.tf32.tf32.f32 "
        "{%0,%1,%2,%3},{%4,%5,%6,%7},{%8,%9},{%0,%1,%2,%3};"
        : "+f"(c[0]), "+f"(c[1]), "+f"(c[2]), "+f"(c[3])
        : "r"(a[0]), "r"(a[1]), "r"(a[2]), "r"(a[3]), "r"(b.x), "r"(b.y));
}

// ---------------- preprocessing ----------------
__global__ void init_kernel() {
    int i = blockIdx.x * blockDim.x + threadIdx.x;
    if (i < NN) g_deg[i] = 0;
    if (i < 3) g_roleCnt[i] = 0;
    if (i < PERM_SZ) g_perm[i] = -1;
}

__global__ void count_kernel(const int* __restrict__ ei, const int* __restrict__ role) {
    int e = blockIdx.x * blockDim.x + threadIdx.x;
    if (e < ET) {
        int c = (e < EE) ? ei[EE + e] : (e - EE);
        atomicAdd(&g_deg[c], 1);
    }
    if (e < NN) atomicAdd(&g_roleCnt[role[e]], 1);
}

__global__ void scan_kernel() {
    __shared__ int warpsum[32];
    __shared__ int s_tot;
    __shared__ int s_carry;
    int t = threadIdx.x, lane = t & 31, w = t >> 5;
    if (t == 0) s_carry = 0;
    __syncthreads();
    for (int base = 0; base < NN; base += 1024) {
        int v = (base + t < NN) ? g_deg[base + t] : 0;
        int s = v;
#pragma unroll
        for (int o = 1; o < 32; o <<= 1) {
            int n = __shfl_up_sync(~0u, s, o);
            if (lane >= o) s += n;
        }
        if (lane == 31) warpsum[w] = s;
        __syncthreads();
        if (w == 0) {
            int ws = warpsum[lane];
            int t2 = ws;
#pragma unroll
            for (int o = 1; o < 32; o <<= 1) {
                int n = __shfl_up_sync(~0u, t2, o);
                if (lane >= o) t2 += n;
            }
            warpsum[lane] = t2 - ws;
            if (lane == 31) s_tot = t2;
        }
        __syncthreads();
        int excl = s_carry + warpsum[w] + s - v;
        if (base + t < NN) {
            g_off[base + t] = excl;
            g_pos[base + t] = excl;
        }
        __syncthreads();
        if (t == 0) s_carry += s_tot;
        __syncthreads();
    }
    if (t == 0) {
        g_off[NN] = s_carry;
        int o = 0;
        for (int r2 = 0; r2 < 3; r2++) {
            g_rolePadOff[r2] = o;
            g_rolePos[r2] = o;
            o += ((g_roleCnt[r2] + 127) >> 7) << 7;
        }
        g_rolePadOff[3] = o;
    }
}

__global__ void fill_kernel(const int* __restrict__ ei, const int* __restrict__ role) {
    int e = blockIdx.x * blockDim.x + threadIdx.x;
    if (e < ET) {
        int r, c;
        if (e < EE) { r = ei[e]; c = ei[EE + e]; }
        else { r = e - EE; c = e - EE; }
        int p = atomicAdd(&g_pos[c], 1);
        g_csr[p] = r;
    }
    if (e < NN) {
        int q = atomicAdd(&g_rolePos[role[e]], 1);
        g_perm[q] = e;
    }
}

// ---------------- WS[conv][r] = W @ S[r] (fp32 exact, tiny) ----------------
__global__ void __launch_bounds__(256) ws_all_kernel(
    const float* W0, const float* S0, const float* W1, const float* S1,
    const float* W2, const float* S2, const float* W3, const float* S3,
    const float* W4, const float* S4, const float* W5, const float* S5) {
    int conv = blockIdx.z, r = blockIdx.y, ct = blockIdx.x;
    const float* W;
    const float* S;
    switch (conv) {
        case 0: W = W0; S = S0; break;
        case 1: W = W1; S = S1; break;
        case 2: W = W2; S = S2; break;
        case 3: W = W3; S = S3; break;
        case 4: W = W4; S = S4; break;
        default: W = W5; S = S5; break;
    }
    const float* B = S + ((size_t)r << 14) + ct * 32;
    float* C = g_WS + (((size_t)conv * 3 + r) << 14) + ct * 32;

    __shared__ float As[DHD][33];
    __shared__ float Bs[32][33];
    int tid = threadIdx.x;
    int tr = tid >> 4, tc = tid & 15;
    float acc[8][2] = {};
    for (int kc = 0; kc < DHD; kc += 32) {
#pragma unroll
        for (int t = 0; t < 4; t++) {
            int idx = tid + t * 256;
            int row = idx >> 3;
            int kq = (idx & 7) << 2;
            float4 v = *(const float4*)&W[(size_t)row * DHD + kc + kq];
            As[row][kq] = v.x; As[row][kq + 1] = v.y; As[row][kq + 2] = v.z; As[row][kq + 3] = v.w;
        }
#pragma unroll
        for (int t = 0; t < 4; t++) {
            int idx = tid + t * 256;
            int kk = idx >> 5;
            int j = idx & 31;
            Bs[kk][j] = B[(size_t)(kc + kk) * DHD + j];
        }
        __syncthreads();
#pragma unroll 8
        for (int kk = 0; kk < 32; kk++) {
            float b0 = Bs[kk][tc * 2], b1 = Bs[kk][tc * 2 + 1];
#pragma unroll
            for (int i = 0; i < 8; i++) {
                float a = As[tr * 8 + i][kk];
                acc[i][0] += a * b0;
                acc[i][1] += a * b1;
            }
        }
        __syncthreads();
    }
#pragma unroll
    for (int i = 0; i < 8; i++) {
        C[(size_t)(tr * 8 + i) * DHD + tc * 2] = acc[i][0];
        C[(size_t)(tr * 8 + i) * DHD + tc * 2 + 1] = acc[i][1];
    }
}

// ---------------- build tf32 fragment-ordered B images ----------------
__global__ void __launch_bounds__(256) img_kernel(const float* W0, const float* W1,
                                                  const float* W2, const float* W3,
                                                  const float* W4, const float* W5) {
    int m = blockIdx.x;
    const float* src;
    switch (m) {
        case 0: src = W0; break;
        case 1: src = W1; break;
        case 2: src = W2; break;
        case 3: src = W3; break;
        case 4: src = W4; break;
        case 5: src = W5; break;
        default: src = g_WS + (size_t)(m - 6) * 16384; break;
    }
    uint32_t* dst = g_Bimg + (size_t)m * 16384;
    for (int i = threadIdx.x; i < 16384; i += 256) {
        int l2 = i & 63;
        int nt = (i >> 6) & 15;
        int kit = i >> 10;
        int lane = l2 >> 1, half = l2 & 1;
        int k = kit * 8 + (lane & 3) + half * 4;
        int n = nt * 8 + (lane >> 2);
        dst[i] = f2tf32(src[k * DHD + n]);
    }
}

// ---------------- tf32 tensor-core GEMM mainloop ----------------
__device__ __forceinline__ void gemm_mainloop(float (*acc)[8][4], uint32_t* sm,
                                              const float* __restrict__ Xp,
                                              const int* rows, int matIdx, int tid) {
    int lane = tid & 31, wid = tid >> 5;
    int warp_m = wid & 3, warp_n = wid >> 2;
    uint32_t* sAhi = sm + OFF_AHI;
    uint32_t* sAlo = sm + OFF_ALO;
    uint32_t* sB = sm + OFF_B;

    for (int kc = 0; kc < 2; kc++) {
        if (kc) __syncthreads();
#pragma unroll
        for (int it = 0; it < 8; it++) {
            int i = tid + it * 256;
            int row = i >> 4, f4 = i & 15;
            int gr = rows[row];
            float4 v = make_float4(0.f, 0.f, 0.f, 0.f);
            if (gr >= 0) v = *(const float4*)(Xp + (size_t)gr * DHD + kc * 64 + f4 * 4);
            int base = row * SA_STRIDE + f4 * 4;
            uint32_t h0, l0, h1, l1, h2, l2, h3, l3;
            split_tf32(v.x, h0, l0);
            split_tf32(v.y, h1, l1);
            split_tf32(v.z, h2, l2);
            split_tf32(v.w, h3, l3);
            *(uint4*)(sAhi + base) = make_uint4(h0, h1, h2, h3);
            *(uint4*)(sAlo + base) = make_uint4(l0, l1, l2, l3);
        }
        const uint4* bsrc = (const uint4*)(g_Bimg + (size_t)matIdx * 16384 + kc * 8192);
#pragma unroll
        for (int it = 0; it < 8; it++) {
            ((uint4*)sB)[tid + it * 256] = bsrc[tid + it * 256];
        }
        __syncthreads();

#pragma unroll
        for (int kit = 0; kit < 8; kit++) {
            uint32_t ah[2][4], al[2][4];
#pragma unroll
            for (int mt = 0; mt < 2; mt++) {
                int r0 = warp_m * 32 + mt * 16 + (lane >> 2);
                int kk = kit * 8 + (lane & 3);
                ah[mt][0] = sAhi[r0 * SA_STRIDE + kk];
                ah[mt][1] = sAhi[(r0 + 8) * SA_STRIDE + kk];
                ah[mt][2] = sAhi[r0 * SA_STRIDE + kk + 4];
                ah[mt][3] = sAhi[(r0 + 8) * SA_STRIDE + kk + 4];
                al[mt][0] = sAlo[r0 * SA_STRIDE + kk];
                al[mt][1] = sAlo[(r0 + 8) * SA_STRIDE + kk];
                al[mt][2] = sAlo[r0 * SA_STRIDE + kk + 4];
                al[mt][3] = sAlo[(r0 + 8) * SA_STRIDE + kk + 4];
            }
#pragma unroll
            for (int nt = 0; nt < 8; nt++) {
                int gnt = warp_n * 8 + nt;
                uint2 b = *(uint2*)(sB + (kit * 16 + gnt) * 64 + lane * 2);
#pragma unroll
                for (int mt = 0; mt < 2; mt++) {
                    mma8(acc[mt][nt], ah[mt], b);
                    mma8(acc[mt][nt], al[mt], b);
                }
            }
        }
    }
}

// ---------------- GEMM: Y = gate(X @ W) + b  (bf16 output) ----------------
__global__ void __launch_bounds__(256) gemm_y_tc(const float* __restrict__ X, int matIdx,
                                                 const float* __restrict__ Wg,
                                                 const float* __restrict__ bg,
                                                 const float* __restrict__ bvec,
                                                 const int* __restrict__ role) {
    extern __shared__ __align__(16) uint32_t sm[];
    __shared__ float sg[3][DHD];
    __shared__ float bb[3][DHD];
    __shared__ int role_s[DHD];
    __shared__ int rows[DHD];

    int tid = threadIdx.x;
    int r0 = blockIdx.x * DHD;
    const float* Xp = X ? X : g_rh;

    for (int t = tid; t < 3 * DHD; t += 256) {
        int r = t >> 7, c = t & 127;
        float wv = Wg[t] + bg[t];
        sg[r][c] = 1.0f / (1.0f + __expf(-wv));
        bb[r][c] = bvec ? bvec[t] : 0.0f;
    }
    if (tid < DHD) {
        int gr = r0 + tid;
        rows[tid] = (gr < NN) ? gr : -1;
        role_s[tid] = (gr < NN) ? role[gr] : 0;
    }
    __syncthreads();

    float acc[2][8][4];
#pragma unroll
    for (int a = 0; a < 2; a++)
#pragma unroll
        for (int b = 0; b < 8; b++)
#pragma unroll
            for (int c = 0; c < 4; c++) acc[a][b][c] = 0.f;

    gemm_mainloop(acc, sm, Xp, rows, matIdx, tid);

    int lane = tid & 31, wid = tid >> 5;
    int warp_m = wid & 3, warp_n = wid >> 2;
#pragma unroll
    for (int mt = 0; mt < 2; mt++) {
#pragma unroll
        for (int h = 0; h < 2; h++) {
            int lrow = warp_m * 32 + mt * 16 + (lane >> 2) + h * 8;
            int grow = r0 + lrow;
            if (grow >= NN) continue;
            int rl = role_s[lrow];
            __nv_bfloat16* yp = g_y + (size_t)grow * DHD;
#pragma unroll
            for (int nt = 0; nt < 8; nt++) {
                int col = warp_n * 64 + nt * 8 + (lane & 3) * 2;
                float v0 = acc[mt][nt][h * 2] * sg[rl][col] + bb[rl][col];
                float v1 = acc[mt][nt][h * 2 + 1] * sg[rl][col + 1] + bb[rl][col + 1];
                *(__nv_bfloat162*)(yp + col) = __float22bfloat162_rn(make_float2(v0, v1));
            }
        }
    }
}

// ---------------- GEMM: C[node] += X[node] @ WS[conv][role] ----------------
__global__ void __launch_bounds__(256) gemm_self_tc(const float* __restrict__ X, int convIdx,
                                                    int sel) {
    int rowBase = blockIdx.x * DHD;
    if (rowBase >= g_rolePadOff[3]) return;
    extern __shared__ __align__(16) uint32_t sm[];
    __shared__ int rows[DHD];

    float* C = sel ? g_bufB : g_bufA;
    const float* Xp = X ? X : g_rh;
    int tid = threadIdx.x;

    int r = 0;
    if (rowBase >= g_rolePadOff[1]) r = 1;
    if (rowBase >= g_rolePadOff[2]) r = 2;
    int matIdx = 6 + convIdx * 3 + r;

    if (tid < DHD) rows[tid] = (rowBase + tid < PERM_SZ) ? g_perm[rowBase + tid] : -1;
    __syncthreads();

    float acc[2][8][4];
#pragma unroll
    for (int a = 0; a < 2; a++)
#pragma unroll
        for (int b = 0; b < 8; b++)
#pragma unroll
            for (int c = 0; c < 4; c++) acc[a][b][c] = 0.f;

    gemm_mainloop(acc, sm, Xp, rows, matIdx, tid);

    int lane = tid & 31, wid = tid >> 5;
    int warp_m = wid & 3, warp_n = wid >> 2;
#pragma unroll
    for (int mt = 0; mt < 2; mt++) {
#pragma unroll
        for (int h = 0; h < 2; h++) {
            int lrow = warp_m * 32 + mt * 16 + (lane >> 2) + h * 8;
            int node = rows[lrow];
            if (node < 0) continue;
            float* cp = C + (size_t)node * DHD;
#pragma unroll
            for (int nt = 0; nt < 8; nt++) {
                int col = warp_n * 64 + nt * 8 + (lane & 3) * 2;
                float2 o = *(float2*)(cp + col);
                o.x += acc[mt][nt][h * 2];
                o.y += acc[mt][nt][h * 2 + 1];
                *(float2*)(cp + col) = o;
            }
        }
    }
}

// ---------------- SpMM: C[i] = mean of bf16 Y[src] over incoming edges ----------------
__global__ void __launch_bounds__(256) spmm_kernel(int sel) {
    float* C = sel ? g_bufB : g_bufA;
    int w = (blockIdx.x * blockDim.x + threadIdx.x) >> 5;
    int lane = threadIdx.x & 31;
    if (w >= NN) return;
    int s = g_off[w], e = g_off[w + 1];
    float4 a0 = make_float4(0.f, 0.f, 0.f, 0.f);
    float4 a1 = make_float4(0.f, 0.f, 0.f, 0.f);
    int p = s;
    for (; p + 2 <= e; p += 2) {
        int s0 = g_csr[p], s1 = g_csr[p + 1];
        uint2 u0 = ((const uint2*)(g_y + (size_t)s0 * DHD))[lane];
        uint2 u1 = ((const uint2*)(g_y + (size_t)s1 * DHD))[lane];
        float2 f00 = __bfloat1622float2(*(__nv_bfloat162*)&u0.x);
        float2 f01 = __bfloat1622float2(*(__nv_bfloat162*)&u0.y);
        float2 f10 = __bfloat1622float2(*(__nv_bfloat162*)&u1.x);
        float2 f11 = __bfloat1622float2(*(__nv_bfloat162*)&u1.y);
        a0.x += f00.x; a0.y += f00.y; a0.z += f01.x; a0.w += f01.y;
        a1.x += f10.x; a1.y += f10.y; a1.z += f11.x; a1.w += f11.y;
    }
    if (p < e) {
        int s0 = g_csr[p];
        uint2 u0 = ((const uint2*)(g_y + (size_t)s0 * DHD))[lane];
        float2 f00 = __bfloat1622float2(*(__nv_bfloat162*)&u0.x);
        float2 f01 = __bfloat1622float2(*(__nv_bfloat162*)&u0.y);
        a0.x += f00.x; a0.y += f00.y; a0.z += f01.x; a0.w += f01.y;
    }
    float inv = 1.0f / (float)(e - s);
    float4 r;
    r.x = (a0.x + a1.x) * inv;
    r.y = (a0.y + a1.y) * inv;
    r.z = (a0.z + a1.z) * inv;
    r.w = (a0.w + a1.w) * inv;
    *(float4*)(C + (size_t)w * DHD + (lane << 2)) = r;
}

// ---------------- elementwise combines ----------------
__device__ __forceinline__ float sigm(float x) { return 1.0f / (1.0f + __expf(-x)); }

__global__ void combine_zr_kernel(const float* __restrict__ h, int mode) {
    size_t i = (size_t)blockIdx.x * blockDim.x + threadIdx.x;
    if (i >= (size_t)NN * 32) return;
    float4 a = ((const float4*)g_bufA)[i];
    float4 b = ((const float4*)g_bufB)[i];
    float4 o;
    o.x = sigm(fmaxf(a.x, 0.f) + fmaxf(b.x, 0.f));
    o.y = sigm(fmaxf(a.y, 0.f) + fmaxf(b.y, 0.f));
    o.z = sigm(fmaxf(a.z, 0.f) + fmaxf(b.z, 0.f));
    o.w = sigm(fmaxf(a.w, 0.f) + fmaxf(b.w, 0.f));
    if (mode) {
        float4 hv = ((const float4*)h)[i];
        o.x *= hv.x; o.y *= hv.y; o.z *= hv.z; o.w *= hv.w;
        ((float4*)g_rh)[i] = o;
    } else {
        ((float4*)g_z)[i] = o;
    }
}

__global__ void combine_h_kernel(const float* __restrict__ h, float* __restrict__ out) {
    size_t i = (size_t)blockIdx.x * blockDim.x + threadIdx.x;
    if (i >= (size_t)NN * 32) return;
    float4 a = ((const float4*)g_bufA)[i];
    float4 b = ((const float4*)g_bufB)[i];
    float4 zv = ((const float4*)g_z)[i];
    float4 hv = ((const float4*)h)[i];
    float4 o;
    float ht;
    ht = tanhf(fmaxf(a.x, 0.f) + fmaxf(b.x, 0.f));
    o.x = zv.x * hv.x + (1.0f - zv.x) * ht;
    ht = tanhf(fmaxf(a.y, 0.f) + fmaxf(b.y, 0.f));
    o.y = zv.y * hv.y + (1.0f - zv.y) * ht;
    ht = tanhf(fmaxf(a.z, 0.f) + fmaxf(b.z, 0.f));
    o.z = zv.z * hv.z + (1.0f - zv.z) * ht;
    ht = tanhf(fmaxf(a.w, 0.f) + fmaxf(b.w, 0.f));
    o.w = zv.w * hv.w + (1.0f - zv.w) * ht;
    ((float4*)out)[i] = o;
}

// ---------------- host launch ----------------
struct CW {
    const float *W, *Wg, *bg, *S, *b;
};

static void run_conv(const float* X, const CW& w, int convIdx, int sel, const int* role) {
    gemm_y_tc<<<GEMM_BLKS, 256, GEMM_SMEM>>>(X, convIdx, w.Wg, w.bg, w.b, role);
    spmm_kernel<<<(NN * 32 + 255) / 256, 256>>>(sel);
    gemm_self_tc<<<SELF_BLKS, 256, GEMM_SMEM>>>(X, convIdx, sel);
}

extern "C" void kernel_launch(void* const* d_in, const int* in_sizes, int n_in,
                              void* d_out, int out_size) {
    cudaFuncSetAttribute(gemm_y_tc, cudaFuncAttributeMaxDynamicSharedMemorySize, GEMM_SMEM);
    cudaFuncSetAttribute(gemm_self_tc, cudaFuncAttributeMaxDynamicSharedMemorySize, GEMM_SMEM);

    int iEdge = 2, iH = 1;
    if (in_sizes[1] == 2 * EE) { iEdge = 1; iH = 2; }
    const float* x = (const float*)d_in[0];
    const float* h_prev = (const float*)d_in[iH];
    const int* ei = (const int*)d_in[iEdge];
    const int* role = (const int*)d_in[3];

    const float* P[27];
    for (int i = 0; i < 27 && (4 + i) < n_in; i++) P[i] = (const float*)d_in[4 + i];
    CW xz{P[0], P[1], P[2], P[3], P[4]};
    CW hz{P[5], P[6], P[7], P[8], nullptr};
    CW xr{P[9], P[10], P[11], P[12], P[13]};
    CW hr{P[14], P[15], P[16], P[17], nullptr};
    CW xh{P[18], P[19], P[20], P[21], P[22]};
    CW hh{P[23], P[24], P[25], P[26], nullptr};
    float* out = (float*)d_out;

    init_kernel<<<(PERM_SZ + 255) / 256, 256>>>();
    count_kernel<<<(ET + 255) / 256, 256>>>(ei, role);
    scan_kernel<<<1, 1024>>>();
    fill_kernel<<<(ET + 255) / 256, 256>>>(ei, role);
    ws_all_kernel<<<dim3(4, 3, 6), 256>>>(xz.W, xz.S, hz.W, hz.S, xr.W, xr.S,
                                          hr.W, hr.S, xh.W, xh.S, hh.W, hh.S);
    img_kernel<<<24, 256>>>(xz.W, hz.W, xr.W, hr.W, xh.W, hh.W);

    // z gate
    run_conv(x, xz, 0, 0, role);
    run_conv(h_prev, hz, 1, 1, role);
    combine_zr_kernel<<<(NN * 32 + 255) / 256, 256>>>(h_prev, 0);
    // r gate -> r * h_prev
    run_conv(x, xr, 2, 0, role);
    run_conv(h_prev, hr, 3, 1, role);
    combine_zr_kernel<<<(NN * 32 + 255) / 256, 256>>>(h_prev, 1);
    // h_tilde + final GRU mix
    run_conv(x, xh, 4, 0, role);
    run_conv(nullptr, hh, 5, 1, role);
    combine_h_kernel<<<(NN * 32 + 255) / 256, 256>>>(h_prev, out);
}

// round 10
// speedup vs baseline: 1.5501x; 1.2360x over previous
#include <cuda_runtime.h>
#include <cuda_bf16.h>
#include <cstdint>

// Problem constants
#define NN 50000
#define EE 1600000
#define ET (EE + NN)
#define DHD 128
#define PERM_SZ (NN + 3 * 128)
#define RB ((NN + 127) / 128)       // 391
#define SB ((PERM_SZ + 127) / 128)  // 396

// Dynamic smem (words): Ahi[128][68] | Alo[128][68] | Bfrag chunk [8][16][64]
#define SA_STRIDE 68
#define OFF_ALO (128 * SA_STRIDE)
#define OFF_B (2 * 128 * SA_STRIDE)
#define GEMM_SMEM ((2 * 128 * SA_STRIDE + 8 * 16 * 64) * 4)  // 102400 B

// ---------------- device scratch ----------------
__device__ __nv_bfloat16 g_yX[(size_t)NN * 384];   // gated X-side messages (xz|xr|xh)
__device__ __nv_bfloat16 g_yH[(size_t)NN * 256];   // gated h-side messages (hz|hr)
__device__ __nv_bfloat16 g_yHH[(size_t)NN * 128];  // gated rh messages (hh)
__device__ float g_bufX[(size_t)NN * 384];
__device__ float g_bufH[(size_t)NN * 256];
__device__ float g_bufHH[(size_t)NN * 128];
__device__ float g_z[(size_t)NN * DHD];
__device__ float g_rh[(size_t)NN * DHD];
__device__ float g_WS[18 * DHD * DHD];       // per-conv per-role W@S (plain [k][n])
__device__ float g_gate[6 * 3 * DHD];        // sigmoid(Wg+bg) per conv/role
__device__ uint32_t g_Bimg[24 * DHD * DHD];  // tf32 fragment-ordered B images
__device__ int g_deg[NN];
__device__ int g_off[NN + 1];
__device__ int g_pos[NN];
__device__ int g_csr[ET];
__device__ int g_roleCnt[3];
__device__ int g_rolePadOff[4];
__device__ int g_rolePos[3];
__device__ int g_perm[PERM_SZ];

// ---------------- tf32 helpers ----------------
__device__ __forceinline__ uint32_t f2tf32(float x) {
    uint32_t r;
    asm("cvt.rna.tf32.f32 %0, %1;" : "=r"(r) : "f"(x));
    return r;
}
__device__ __forceinline__ void split_tf32(float x, uint32_t& hi, uint32_t& lo) {
    asm("cvt.rna.tf32.f32 %0, %1;" : "=r"(hi) : "f"(x));
    float r = x - __uint_as_float(hi);
    asm("cvt.rna.tf32.f32 %0, %1;" : "=r"(lo) : "f"(r));
}
__device__ __forceinline__ void mma8(float* c, const uint32_t* a, uint2 b) {
    asm volatile(
        "mma.sync.aligned.m16n8k8.row.col.f32.tf32.tf32.f32 "
        "{%0,%1,%2,%3},{%4,%5,%6,%7},{%8,%9},{%0,%1,%2,%3};"
        : "+f"(c[0]), "+f"(c[1]), "+f"(c[2]), "+f"(c[3])
        : "r"(a[0]), "r"(a[1]), "r"(a[2]), "r"(a[3]), "r"(b.x), "r"(b.y));
}

// ---------------- preprocessing ----------------
__global__ void init_kernel() {
    int i = blockIdx.x * blockDim.x + threadIdx.x;
    if (i < NN) g_deg[i] = 0;
    if (i < 3) g_roleCnt[i] = 0;
    if (i < PERM_SZ) g_perm[i] = -1;
}

__global__ void count_kernel(const int* __restrict__ ei, const int* __restrict__ role) {
    int e = blockIdx.x * blockDim.x + threadIdx.x;
    if (e < ET) {
        int c = (e < EE) ? ei[EE + e] : (e - EE);
        atomicAdd(&g_deg[c], 1);
    }
    if (e < NN) atomicAdd(&g_roleCnt[role[e]], 1);
}

__global__ void scan_kernel() {
    __shared__ int warpsum[32];
    __shared__ int s_tot;
    __shared__ int s_carry;
    int t = threadIdx.x, lane = t & 31, w = t >> 5;
    if (t == 0) s_carry = 0;
    __syncthreads();
    for (int base = 0; base < NN; base += 1024) {
        int v = (base + t < NN) ? g_deg[base + t] : 0;
        int s = v;
#pragma unroll
        for (int o = 1; o < 32; o <<= 1) {
            int n = __shfl_up_sync(~0u, s, o);
            if (lane >= o) s += n;
        }
        if (lane == 31) warpsum[w] = s;
        __syncthreads();
        if (w == 0) {
            int ws = warpsum[lane];
            int t2 = ws;
#pragma unroll
            for (int o = 1; o < 32; o <<= 1) {
                int n = __shfl_up_sync(~0u, t2, o);
                if (lane >= o) t2 += n;
            }
            warpsum[lane] = t2 - ws;
            if (lane == 31) s_tot = t2;
        }
        __syncthreads();
        int excl = s_carry + warpsum[w] + s - v;
        if (base + t < NN) {
            g_off[base + t] = excl;
            g_pos[base + t] = excl;
        }
        __syncthreads();
        if (t == 0) s_carry += s_tot;
        __syncthreads();
    }
    if (t == 0) {
        g_off[NN] = s_carry;
        int o = 0;
        for (int r2 = 0; r2 < 3; r2++) {
            g_rolePadOff[r2] = o;
            g_rolePos[r2] = o;
            o += ((g_roleCnt[r2] + 127) >> 7) << 7;
        }
        g_rolePadOff[3] = o;
    }
}

__global__ void fill_kernel(const int* __restrict__ ei, const int* __restrict__ role) {
    int e = blockIdx.x * blockDim.x + threadIdx.x;
    if (e < ET) {
        int r, c;
        if (e < EE) { r = ei[e]; c = ei[EE + e]; }
        else { r = e - EE; c = e - EE; }
        int p = atomicAdd(&g_pos[c], 1);
        g_csr[p] = r;
    }
    if (e < NN) {
        int q = atomicAdd(&g_rolePos[role[e]], 1);
        g_perm[q] = e;
    }
}

// gates: sigmoid(Wg + bg) for all 6 convs (order: xz,hz,xr,hr,xh,hh)
__global__ void gates_kernel(const float* g0, const float* b0, const float* g1, const float* b1,
                             const float* g2, const float* b2, const float* g3, const float* b3,
                             const float* g4, const float* b4, const float* g5, const float* b5) {
    int c = blockIdx.x, t = threadIdx.x;
    const float* gp;
    const float* bp;
    switch (c) {
        case 0: gp = g0; bp = b0; break;
        case 1: gp = g1; bp = b1; break;
        case 2: gp = g2; bp = b2; break;
        case 3: gp = g3; bp = b3; break;
        case 4: gp = g4; bp = b4; break;
        default: gp = g5; bp = b5; break;
    }
    float v = gp[t] + bp[t];
    g_gate[c * 384 + t] = 1.0f / (1.0f + __expf(-v));
}

// ---------------- WS[conv][r] = W @ S[r] (fp32 exact, tiny) ----------------
__global__ void __launch_bounds__(256) ws_all_kernel(
    const float* W0, const float* S0, const float* W1, const float* S1,
    const float* W2, const float* S2, const float* W3, const float* S3,
    const float* W4, const float* S4, const float* W5, const float* S5) {
    int conv = blockIdx.z, r = blockIdx.y, ct = blockIdx.x;
    const float* W;
    const float* S;
    switch (conv) {
        case 0: W = W0; S = S0; break;
        case 1: W = W1; S = S1; break;
        case 2: W = W2; S = S2; break;
        case 3: W = W3; S = S3; break;
        case 4: W = W4; S = S4; break;
        default: W = W5; S = S5; break;
    }
    const float* B = S + ((size_t)r << 14) + ct * 32;
    float* C = g_WS + (((size_t)conv * 3 + r) << 14) + ct * 32;

    __shared__ float As[DHD][33];
    __shared__ float Bs[32][33];
    int tid = threadIdx.x;
    int tr = tid >> 4, tc = tid & 15;
    float acc[8][2] = {};
    for (int kc = 0; kc < DHD; kc += 32) {
#pragma unroll
        for (int t = 0; t < 4; t++) {
            int idx = tid + t * 256;
            int row = idx >> 3;
            int kq = (idx & 7) << 2;
            float4 v = *(const float4*)&W[(size_t)row * DHD + kc + kq];
            As[row][kq] = v.x; As[row][kq + 1] = v.y; As[row][kq + 2] = v.z; As[row][kq + 3] = v.w;
        }
#pragma unroll
        for (int t = 0; t < 4; t++) {
            int idx = tid + t * 256;
            int kk = idx >> 5;
            int j = idx & 31;
            Bs[kk][j] = B[(size_t)(kc + kk) * DHD + j];
        }
        __syncthreads();
#pragma unroll 8
        for (int kk = 0; kk < 32; kk++) {
            float b0 = Bs[kk][tc * 2], b1 = Bs[kk][tc * 2 + 1];
#pragma unroll
            for (int i = 0; i < 8; i++) {
                float a = As[tr * 8 + i][kk];
                acc[i][0] += a * b0;
                acc[i][1] += a * b1;
            }
        }
        __syncthreads();
    }
#pragma unroll
    for (int i = 0; i < 8; i++) {
        C[(size_t)(tr * 8 + i) * DHD + tc * 2] = acc[i][0];
        C[(size_t)(tr * 8 + i) * DHD + tc * 2 + 1] = acc[i][1];
    }
}

// ---------------- build tf32 fragment-ordered B images ----------------
__global__ void __launch_bounds__(256) img_kernel(const float* W0, const float* W1,
                                                  const float* W2, const float* W3,
                                                  const float* W4, const float* W5) {
    int m = blockIdx.x;
    const float* src;
    switch (m) {
        case 0: src = W0; break;
        case 1: src = W1; break;
        case 2: src = W2; break;
        case 3: src = W3; break;
        case 4: src = W4; break;
        case 5: src = W5; break;
        default: src = g_WS + (size_t)(m - 6) * 16384; break;
    }
    uint32_t* dst = g_Bimg + (size_t)m * 16384;
    for (int i = threadIdx.x; i < 16384; i += 256) {
        int l2 = i & 63;
        int nt = (i >> 6) & 15;
        int kit = i >> 10;
        int lane = l2 >> 1, half = l2 & 1;
        int k = kit * 8 + (lane & 3) + half * 4;
        int n = nt * 8 + (lane >> 2);
        dst[i] = f2tf32(src[k * DHD + n]);
    }
}

// ---------------- tf32 tensor-core GEMM mainloop ----------------
__device__ __forceinline__ void gemm_mainloop(float (*acc)[8][4], uint32_t* sm,
                                              const float* __restrict__ Xp,
                                              const int* rows, int matIdx, int tid) {
    int lane = tid & 31, wid = tid >> 5;
    int warp_m = wid & 3, warp_n = wid >> 2;
    uint32_t* sAhi = sm;
    uint32_t* sAlo = sm + OFF_ALO;
    uint32_t* sB = sm + OFF_B;

    for (int kc = 0; kc < 2; kc++) {
        if (kc) __syncthreads();
#pragma unroll
        for (int it = 0; it < 8; it++) {
            int i = tid + it * 256;
            int row = i >> 4, f4 = i & 15;
            int gr = rows[row];
            float4 v = make_float4(0.f, 0.f, 0.f, 0.f);
            if (gr >= 0) v = *(const float4*)(Xp + (size_t)gr * DHD + kc * 64 + f4 * 4);
            int base = row * SA_STRIDE + f4 * 4;
            uint32_t h0, l0, h1, l1, h2, l2, h3, l3;
            split_tf32(v.x, h0, l0);
            split_tf32(v.y, h1, l1);
            split_tf32(v.z, h2, l2);
            split_tf32(v.w, h3, l3);
            *(uint4*)(sAhi + base) = make_uint4(h0, h1, h2, h3);
            *(uint4*)(sAlo + base) = make_uint4(l0, l1, l2, l3);
        }
        const uint4* bsrc = (const uint4*)(g_Bimg + (size_t)matIdx * 16384 + kc * 8192);
#pragma unroll
        for (int it = 0; it < 8; it++) {
            ((uint4*)sB)[tid + it * 256] = bsrc[tid + it * 256];
        }
        __syncthreads();

#pragma unroll
        for (int kit = 0; kit < 8; kit++) {
            uint32_t ah[2][4], al[2][4];
#pragma unroll
            for (int mt = 0; mt < 2; mt++) {
                int r0 = warp_m * 32 + mt * 16 + (lane >> 2);
                int kk = kit * 8 + (lane & 3);
                ah[mt][0] = sAhi[r0 * SA_STRIDE + kk];
                ah[mt][1] = sAhi[(r0 + 8) * SA_STRIDE + kk];
                ah[mt][2] = sAhi[r0 * SA_STRIDE + kk + 4];
                ah[mt][3] = sAhi[(r0 + 8) * SA_STRIDE + kk + 4];
                al[mt][0] = sAlo[r0 * SA_STRIDE + kk];
                al[mt][1] = sAlo[(r0 + 8) * SA_STRIDE + kk];
                al[mt][2] = sAlo[r0 * SA_STRIDE + kk + 4];
                al[mt][3] = sAlo[(r0 + 8) * SA_STRIDE + kk + 4];
            }
#pragma unroll
            for (int nt = 0; nt < 8; nt++) {
                int gnt = warp_n * 8 + nt;
                uint2 b = *(uint2*)(sB + (kit * 16 + gnt) * 64 + lane * 2);
#pragma unroll
                for (int mt = 0; mt < 2; mt++) {
                    mma8(acc[mt][nt], ah[mt], b);
                    mma8(acc[mt][nt], al[mt], b);
                }
            }
        }
    }
}

#define DECL_ACC(acc)                     \
    float acc[2][8][4];                   \
    _Pragma("unroll") for (int _a = 0; _a < 2; _a++) _Pragma("unroll") for (int _b = 0;        \
                                                                            _b < 8; _b++)      \
        _Pragma("unroll") for (int _c = 0; _c < 4; _c++) acc[_a][_b][_c] = 0.f;

// ---------------- fused Y GEMMs (bf16 output) ----------------
// mode 0: X -> g_yX [N,384], convs {0,2,4}, with bias
// mode 1: h -> g_yH [N,256], convs {1,3}
// mode 2: rh -> g_yHH [N,128], conv 5
__global__ void __launch_bounds__(256) gemm_y_f(const float* __restrict__ Aext, int mode,
                                                const float* __restrict__ bxz,
                                                const float* __restrict__ bxr,
                                                const float* __restrict__ bxh,
                                                const int* __restrict__ role) {
    extern __shared__ __align__(16) uint32_t sm[];
    __shared__ float sg[DHD * 3];
    __shared__ float bb[DHD * 3];
    __shared__ int role_s[DHD];
    __shared__ int rows[DHD];

    int tid = threadIdx.x, ct = blockIdx.y;
    int r0 = blockIdx.x * DHD;
    const float* Xp = Aext ? Aext : g_rh;

    int conv, ostride;
    __nv_bfloat16* obase;
    const float* bvec = nullptr;
    if (mode == 0) {
        conv = ct * 2;
        ostride = 384;
        obase = g_yX;
        bvec = (ct == 0) ? bxz : ((ct == 1) ? bxr : bxh);
    } else if (mode == 1) {
        conv = 1 + ct * 2;
        ostride = 256;
        obase = g_yH;
    } else {
        conv = 5;
        ostride = 128;
        obase = g_yHH;
    }

    for (int t = tid; t < 3 * DHD; t += 256) {
        sg[t] = g_gate[conv * 384 + t];
        bb[t] = bvec ? bvec[t] : 0.0f;
    }
    if (tid < DHD) {
        int gr = r0 + tid;
        rows[tid] = (gr < NN) ? gr : -1;
        role_s[tid] = (gr < NN) ? role[gr] : 0;
    }
    __syncthreads();

    DECL_ACC(acc)
    gemm_mainloop(acc, sm, Xp, rows, conv, tid);

    int lane = tid & 31, wid = tid >> 5;
    int warp_m = wid & 3, warp_n = wid >> 2;
#pragma unroll
    for (int mt = 0; mt < 2; mt++) {
#pragma unroll
        for (int h = 0; h < 2; h++) {
            int lrow = warp_m * 32 + mt * 16 + (lane >> 2) + h * 8;
            int grow = r0 + lrow;
            if (grow >= NN) continue;
            int rb = role_s[lrow] * 128;
            __nv_bfloat16* yp = obase + (size_t)grow * ostride + ct * 128;
#pragma unroll
            for (int nt = 0; nt < 8; nt++) {
                int col = warp_n * 64 + nt * 8 + (lane & 3) * 2;
                float v0 = acc[mt][nt][h * 2] * sg[rb + col] + bb[rb + col];
                float v1 = acc[mt][nt][h * 2 + 1] * sg[rb + col + 1] + bb[rb + col + 1];
                *(__nv_bfloat162*)(yp + col) = __float22bfloat162_rn(make_float2(v0, v1));
            }
        }
    }
}

// ---------------- fused self GEMMs: buf += A[node] @ WS[conv][role] ----------------
__global__ void __launch_bounds__(256) gemm_self_f(const float* __restrict__ Aext, int mode) {
    int rowBase = blockIdx.x * DHD;
    if (rowBase >= g_rolePadOff[3]) return;
    extern __shared__ __align__(16) uint32_t sm[];
    __shared__ int rows[DHD];

    int tid = threadIdx.x, ct = blockIdx.y;
    const float* Xp = Aext ? Aext : g_rh;

    int r = 0;
    if (rowBase >= g_rolePadOff[1]) r = 1;
    if (rowBase >= g_rolePadOff[2]) r = 2;

    int conv, ostride;
    float* obase;
    if (mode == 0) { conv = ct * 2; ostride = 384; obase = g_bufX; }
    else if (mode == 1) { conv = 1 + ct * 2; ostride = 256; obase = g_bufH; }
    else { conv = 5; ostride = 128; obase = g_bufHH; }
    int matIdx = 6 + conv * 3 + r;

    if (tid < DHD) rows[tid] = (rowBase + tid < PERM_SZ) ? g_perm[rowBase + tid] : -1;
    __syncthreads();

    DECL_ACC(acc)
    gemm_mainloop(acc, sm, Xp, rows, matIdx, tid);

    int lane = tid & 31, wid = tid >> 5;
    int warp_m = wid & 3, warp_n = wid >> 2;
#pragma unroll
    for (int mt = 0; mt < 2; mt++) {
#pragma unroll
        for (int h = 0; h < 2; h++) {
            int lrow = warp_m * 32 + mt * 16 + (lane >> 2) + h * 8;
            int node = rows[lrow];
            if (node < 0) continue;
            float* cp = obase + (size_t)node * ostride + ct * 128;
#pragma unroll
            for (int nt = 0; nt < 8; nt++) {
                int col = warp_n * 64 + nt * 8 + (lane & 3) * 2;
                float2 o = *(float2*)(cp + col);
                o.x += acc[mt][nt][h * 2];
                o.y += acc[mt][nt][h * 2 + 1];
                *(float2*)(cp + col) = o;
            }
        }
    }
}

// ---------------- fused gathers (warp per node) ----------------
__device__ __forceinline__ void bfacc(float4& a, uint2 u) {
    float2 f0 = __bfloat1622float2(*(__nv_bfloat162*)&u.x);
    float2 f1 = __bfloat1622float2(*(__nv_bfloat162*)&u.y);
    a.x += f0.x; a.y += f0.y; a.z += f1.x; a.w += f1.y;
}
__device__ __forceinline__ float4 scale4(float4 a, float s) {
    return make_float4(a.x * s, a.y * s, a.z * s, a.w * s);
}

// SEGS: number of 256B row segments (3 for yX, 2 for yH, 1 for yHH)
template <int SEGS>
__device__ __forceinline__ void gather_body(const __nv_bfloat16* __restrict__ ybase,
                                            float* __restrict__ obase) {
    int w = (blockIdx.x * blockDim.x + threadIdx.x) >> 5;
    int lane = threadIdx.x & 31;
    if (w >= NN) return;
    int s = g_off[w], e = g_off[w + 1];
    float4 a[SEGS];
#pragma unroll
    for (int q = 0; q < SEGS; q++) a[q] = make_float4(0.f, 0.f, 0.f, 0.f);
    int p = s;
    for (; p + 2 <= e; p += 2) {
        int s0 = g_csr[p], s1 = g_csr[p + 1];
        const uint2* b0 = (const uint2*)(ybase + (size_t)s0 * (SEGS * 128));
        const uint2* b1 = (const uint2*)(ybase + (size_t)s1 * (SEGS * 128));
        uint2 u0[SEGS], u1[SEGS];
#pragma unroll
        for (int q = 0; q < SEGS; q++) u0[q] = b0[lane + q * 32];
#pragma unroll
        for (int q = 0; q < SEGS; q++) u1[q] = b1[lane + q * 32];
#pragma unroll
        for (int q = 0; q < SEGS; q++) { bfacc(a[q], u0[q]); bfacc(a[q], u1[q]); }
    }
    if (p < e) {
        int s0 = g_csr[p];
        const uint2* b0 = (const uint2*)(ybase + (size_t)s0 * (SEGS * 128));
#pragma unroll
        for (int q = 0; q < SEGS; q++) bfacc(a[q], b0[lane + q * 32]);
    }
    float inv = 1.0f / (float)(e - s);
    float* o = obase + (size_t)w * (SEGS * 128);
#pragma unroll
    for (int q = 0; q < SEGS; q++)
        *(float4*)(o + q * 128 + lane * 4) = scale4(a[q], inv);
}

__global__ void __launch_bounds__(256) gather_x_kernel() { gather_body<3>(g_yX, g_bufX); }
__global__ void __launch_bounds__(256) gather_h_kernel() { gather_body<2>(g_yH, g_bufH); }
__global__ void __launch_bounds__(256) gather_hh_kernel() { gather_body<1>(g_yHH, g_bufHH); }

// ---------------- combines ----------------
__device__ __forceinline__ float sigm(float x) { return 1.0f / (1.0f + __expf(-x)); }
__device__ __forceinline__ float rl(float x) { return fmaxf(x, 0.f); }

__global__ void combine_zr_kernel(const float* __restrict__ h) {
    size_t idx = (size_t)blockIdx.x * blockDim.x + threadIdx.x;
    if (idx >= (size_t)NN * 32) return;
    size_t i = idx >> 5;
    int q = (int)(idx & 31);
    float4 xz = *(const float4*)(g_bufX + i * 384 + q * 4);
    float4 xr = *(const float4*)(g_bufX + i * 384 + 128 + q * 4);
    float4 hz = *(const float4*)(g_bufH + i * 256 + q * 4);
    float4 hr = *(const float4*)(g_bufH + i * 256 + 128 + q * 4);
    float4 hv = *(const float4*)(h + i * 128 + q * 4);
    float4 z, rr;
    z.x = sigm(rl(xz.x) + rl(hz.x)); z.y = sigm(rl(xz.y) + rl(hz.y));
    z.z = sigm(rl(xz.z) + rl(hz.z)); z.w = sigm(rl(xz.w) + rl(hz.w));
    rr.x = sigm(rl(xr.x) + rl(hr.x)) * hv.x; rr.y = sigm(rl(xr.y) + rl(hr.y)) * hv.y;
    rr.z = sigm(rl(xr.z) + rl(hr.z)) * hv.z; rr.w = sigm(rl(xr.w) + rl(hr.w)) * hv.w;
    *(float4*)(g_z + i * 128 + q * 4) = z;
    *(float4*)(g_rh + i * 128 + q * 4) = rr;
}

__global__ void combine_h_kernel(const float* __restrict__ h, float* __restrict__ out) {
    size_t idx = (size_t)blockIdx.x * blockDim.x + threadIdx.x;
    if (idx >= (size_t)NN * 32) return;
    size_t i = idx >> 5;
    int q = (int)(idx & 31);
    float4 xh = *(const float4*)(g_bufX + i * 384 + 256 + q * 4);
    float4 hh = *(const float4*)(g_bufHH + i * 128 + q * 4);
    float4 zv = *(const float4*)(g_z + i * 128 + q * 4);
    float4 hv = *(const float4*)(h + i * 128 + q * 4);
    float4 o;
    float t;
    t = tanhf(rl(xh.x) + rl(hh.x)); o.x = zv.x * hv.x + (1.f - zv.x) * t;
    t = tanhf(rl(xh.y) + rl(hh.y)); o.y = zv.y * hv.y + (1.f - zv.y) * t;
    t = tanhf(rl(xh.z) + rl(hh.z)); o.z = zv.z * hv.z + (1.f - zv.z) * t;
    t = tanhf(rl(xh.w) + rl(hh.w)); o.w = zv.w * hv.w + (1.f - zv.w) * t;
    *(float4*)(out + i * 128 + q * 4) = o;
}

// ---------------- host launch ----------------
extern "C" void kernel_launch(void* const* d_in, const int* in_sizes, int n_in,
                              void* d_out, int out_size) {
    cudaFuncSetAttribute(gemm_y_f, cudaFuncAttributeMaxDynamicSharedMemorySize, GEMM_SMEM);
    cudaFuncSetAttribute(gemm_self_f, cudaFuncAttributeMaxDynamicSharedMemorySize, GEMM_SMEM);

    int iEdge = 2, iH = 1;
    if (in_sizes[1] == 2 * EE) { iEdge = 1; iH = 2; }
    const float* x = (const float*)d_in[0];
    const float* h_prev = (const float*)d_in[iH];
    const int* ei = (const int*)d_in[iEdge];
    const int* role = (const int*)d_in[3];

    const float* P[27];
    for (int i = 0; i < 27 && (4 + i) < n_in; i++) P[i] = (const float*)d_in[4 + i];
    // xz: W,Wg,bg,S,b = P0..P4 | hz: P5..P8 | xr: P9..P13 | hr: P14..P17
    // xh: P18..P22 | hh: P23..P26
    float* out = (float*)d_out;

    int warpGrid = (NN * 32 + 255) / 256;

    init_kernel<<<(PERM_SZ + 255) / 256, 256>>>();
    count_kernel<<<(ET + 255) / 256, 256>>>(ei, role);
    scan_kernel<<<1, 1024>>>();
    fill_kernel<<<(ET + 255) / 256, 256>>>(ei, role);
    gates_kernel<<<6, 384>>>(P[1], P[2], P[6], P[7], P[10], P[11], P[15], P[16], P[19], P[20],
                             P[24], P[25]);
    ws_all_kernel<<<dim3(4, 3, 6), 256>>>(P[0], P[3], P[5], P[8], P[9], P[12], P[14], P[17],
                                          P[18], P[21], P[23], P[26]);
    img_kernel<<<24, 256>>>(P[0], P[5], P[9], P[14], P[18], P[23]);

    // z + r gates (all independent of rh)
    gemm_y_f<<<dim3(RB, 3), 256, GEMM_SMEM>>>(x, 0, P[4], P[13], P[22], role);
    gemm_y_f<<<dim3(RB, 2), 256, GEMM_SMEM>>>(h_prev, 1, nullptr, nullptr, nullptr, role);
    gather_x_kernel<<<warpGrid, 256>>>();
    gather_h_kernel<<<warpGrid, 256>>>();
    gemm_self_f<<<dim3(SB, 3), 256, GEMM_SMEM>>>(x, 0);
    gemm_self_f<<<dim3(SB, 2), 256, GEMM_SMEM>>>(h_prev, 1);
    combine_zr_kernel<<<warpGrid, 256>>>(h_prev);
    // hh chain (depends on rh)
    gemm_y_f<<<dim3(RB, 1), 256, GEMM_SMEM>>>(nullptr, 2, nullptr, nullptr, nullptr, role);
    gather_hh_kernel<<<warpGrid, 256>>>();
    gemm_self_f<<<dim3(SB, 1), 256, GEMM_SMEM>>>(nullptr, 2);
    combine_h_kernel<<<warpGrid, 256>>>(h_prev, out);
}

// round 11
// speedup vs baseline: 1.6505x; 1.0648x over previous
#include <cuda_runtime.h>
#include <cuda_bf16.h>
#include <cstdint>

// Problem constants
#define NN 50000
#define EE 1600000
#define ET (EE + NN)
#define DHD 128
#define PERM_SZ (NN + 3 * 128)
#define RB ((NN + 127) / 128)       // 391
#define SB ((PERM_SZ + 127) / 128)  // 396

// Dynamic smem (words): Ahi[128][68] | Alo[128][68] | Bfrag chunk [8][16][64]
#define SA_STRIDE 68
#define OFF_ALO (128 * SA_STRIDE)
#define OFF_B (2 * 128 * SA_STRIDE)
#define GEMM_SMEM ((2 * 128 * SA_STRIDE + 8 * 16 * 64) * 4)  // 102400 B

// ---------------- device scratch ----------------
__device__ __nv_bfloat16 g_yX[(size_t)NN * 384];   // gated X-side messages (xz|xr|xh)
__device__ __nv_bfloat16 g_yH[(size_t)NN * 256];   // gated h-side messages (hz|hr)
__device__ __nv_bfloat16 g_yHH[(size_t)NN * 128];  // gated rh messages (hh)
__device__ float g_bufX[(size_t)NN * 384];   // gather results
__device__ float g_bufH[(size_t)NN * 256];
__device__ float g_bufHH[(size_t)NN * 128];
__device__ float g_bufX2[(size_t)NN * 384];  // self-GEMM results (separate: enables overlap)
__device__ float g_bufH2[(size_t)NN * 256];
__device__ float g_bufHH2[(size_t)NN * 128];
__device__ float g_z[(size_t)NN * DHD];
__device__ float g_rh[(size_t)NN * DHD];
__device__ float g_WS[18 * DHD * DHD];       // per-conv per-role W@S (plain [k][n])
__device__ float g_gate[6 * 3 * DHD];        // sigmoid(Wg+bg) per conv/role
__device__ uint32_t g_Bimg[24 * DHD * DHD];  // tf32 fragment-ordered B images
__device__ int g_deg[NN];
__device__ int g_off[NN + 1];
__device__ int g_pos[NN];
__device__ int g_csr[ET];
__device__ int g_roleCnt[3];
__device__ int g_rolePadOff[4];
__device__ int g_rolePos[3];
__device__ int g_perm[PERM_SZ];

// ---------------- tf32 helpers ----------------
__device__ __forceinline__ uint32_t f2tf32(float x) {
    uint32_t r;
    asm("cvt.rna.tf32.f32 %0, %1;" : "=r"(r) : "f"(x));
    return r;
}
__device__ __forceinline__ void split_tf32(float x, uint32_t& hi, uint32_t& lo) {
    asm("cvt.rna.tf32.f32 %0, %1;" : "=r"(hi) : "f"(x));
    float r = x - __uint_as_float(hi);
    asm("cvt.rna.tf32.f32 %0, %1;" : "=r"(lo) : "f"(r));
}
__device__ __forceinline__ void mma8(float* c, const uint32_t* a, uint2 b) {
    asm volatile(
        "mma.sync.aligned.m16n8k8.row.col.f32.tf32.tf32.f32 "
        "{%0,%1,%2,%3},{%4,%5,%6,%7},{%8,%9},{%0,%1,%2,%3};"
        : "+f"(c[0]), "+f"(c[1]), "+f"(c[2]), "+f"(c[3])
        : "r"(a[0]), "r"(a[1]), "r"(a[2]), "r"(a[3]), "r"(b.x), "r"(b.y));
}

// ---------------- preprocessing ----------------
__global__ void init_kernel() {
    int i = blockIdx.x * blockDim.x + threadIdx.x;
    if (i < NN) g_deg[i] = 0;
    if (i < 3) g_roleCnt[i] = 0;
    if (i < PERM_SZ) g_perm[i] = -1;
}

__global__ void count_kernel(const int* __restrict__ ei, const int* __restrict__ role) {
    int e = blockIdx.x * blockDim.x + threadIdx.x;
    if (e < ET) {
        int c = (e < EE) ? ei[EE + e] : (e - EE);
        atomicAdd(&g_deg[c], 1);
    }
    if (e < NN) atomicAdd(&g_roleCnt[role[e]], 1);
}

__global__ void scan_kernel() {
    __shared__ int warpsum[32];
    __shared__ int s_tot;
    __shared__ int s_carry;
    int t = threadIdx.x, lane = t & 31, w = t >> 5;
    if (t == 0) s_carry = 0;
    __syncthreads();
    for (int base = 0; base < NN; base += 1024) {
        int v = (base + t < NN) ? g_deg[base + t] : 0;
        int s = v;
#pragma unroll
        for (int o = 1; o < 32; o <<= 1) {
            int n = __shfl_up_sync(~0u, s, o);
            if (lane >= o) s += n;
        }
        if (lane == 31) warpsum[w] = s;
        __syncthreads();
        if (w == 0) {
            int ws = warpsum[lane];
            int t2 = ws;
#pragma unroll
            for (int o = 1; o < 32; o <<= 1) {
                int n = __shfl_up_sync(~0u, t2, o);
                if (lane >= o) t2 += n;
            }
            warpsum[lane] = t2 - ws;
            if (lane == 31) s_tot = t2;
        }
        __syncthreads();
        int excl = s_carry + warpsum[w] + s - v;
        if (base + t < NN) {
            g_off[base + t] = excl;
            g_pos[base + t] = excl;
        }
        __syncthreads();
        if (t == 0) s_carry += s_tot;
        __syncthreads();
    }
    if (t == 0) {
        g_off[NN] = s_carry;
        int o = 0;
        for (int r2 = 0; r2 < 3; r2++) {
            g_rolePadOff[r2] = o;
            g_rolePos[r2] = o;
            o += ((g_roleCnt[r2] + 127) >> 7) << 7;
        }
        g_rolePadOff[3] = o;
    }
}

__global__ void fill_kernel(const int* __restrict__ ei, const int* __restrict__ role) {
    int e = blockIdx.x * blockDim.x + threadIdx.x;
    if (e < ET) {
        int r, c;
        if (e < EE) { r = ei[e]; c = ei[EE + e]; }
        else { r = e - EE; c = e - EE; }
        int p = atomicAdd(&g_pos[c], 1);
        g_csr[p] = r;
    }
    if (e < NN) {
        int q = atomicAdd(&g_rolePos[role[e]], 1);
        g_perm[q] = e;
    }
}

// gates: sigmoid(Wg + bg) for all 6 convs (order: xz,hz,xr,hr,xh,hh)
__global__ void gates_kernel(const float* g0, const float* b0, const float* g1, const float* b1,
                             const float* g2, const float* b2, const float* g3, const float* b3,
                             const float* g4, const float* b4, const float* g5, const float* b5) {
    int c = blockIdx.x, t = threadIdx.x;
    const float* gp;
    const float* bp;
    switch (c) {
        case 0: gp = g0; bp = b0; break;
        case 1: gp = g1; bp = b1; break;
        case 2: gp = g2; bp = b2; break;
        case 3: gp = g3; bp = b3; break;
        case 4: gp = g4; bp = b4; break;
        default: gp = g5; bp = b5; break;
    }
    float v = gp[t] + bp[t];
    g_gate[c * 384 + t] = 1.0f / (1.0f + __expf(-v));
}

// ---------------- WS[conv][r] = W @ S[r] (fp32 exact, tiny) ----------------
__global__ void __launch_bounds__(256) ws_all_kernel(
    const float* W0, const float* S0, const float* W1, const float* S1,
    const float* W2, const float* S2, const float* W3, const float* S3,
    const float* W4, const float* S4, const float* W5, const float* S5) {
    int conv = blockIdx.z, r = blockIdx.y, ct = blockIdx.x;
    const float* W;
    const float* S;
    switch (conv) {
        case 0: W = W0; S = S0; break;
        case 1: W = W1; S = S1; break;
        case 2: W = W2; S = S2; break;
        case 3: W = W3; S = S3; break;
        case 4: W = W4; S = S4; break;
        default: W = W5; S = S5; break;
    }
    const float* B = S + ((size_t)r << 14) + ct * 32;
    float* C = g_WS + (((size_t)conv * 3 + r) << 14) + ct * 32;

    __shared__ float As[DHD][33];
    __shared__ float Bs[32][33];
    int tid = threadIdx.x;
    int tr = tid >> 4, tc = tid & 15;
    float acc[8][2] = {};
    for (int kc = 0; kc < DHD; kc += 32) {
#pragma unroll
        for (int t = 0; t < 4; t++) {
            int idx = tid + t * 256;
            int row = idx >> 3;
            int kq = (idx & 7) << 2;
            float4 v = *(const float4*)&W[(size_t)row * DHD + kc + kq];
            As[row][kq] = v.x; As[row][kq + 1] = v.y; As[row][kq + 2] = v.z; As[row][kq + 3] = v.w;
        }
#pragma unroll
        for (int t = 0; t < 4; t++) {
            int idx = tid + t * 256;
            int kk = idx >> 5;
            int j = idx & 31;
            Bs[kk][j] = B[(size_t)(kc + kk) * DHD + j];
        }
        __syncthreads();
#pragma unroll 8
        for (int kk = 0; kk < 32; kk++) {
            float b0 = Bs[kk][tc * 2], b1 = Bs[kk][tc * 2 + 1];
#pragma unroll
            for (int i = 0; i < 8; i++) {
                float a = As[tr * 8 + i][kk];
                acc[i][0] += a * b0;
                acc[i][1] += a * b1;
            }
        }
        __syncthreads();
    }
#pragma unroll
    for (int i = 0; i < 8; i++) {
        C[(size_t)(tr * 8 + i) * DHD + tc * 2] = acc[i][0];
        C[(size_t)(tr * 8 + i) * DHD + tc * 2 + 1] = acc[i][1];
    }
}

// ---------------- build tf32 fragment-ordered B images ----------------
__global__ void __launch_bounds__(256) img_kernel(const float* W0, const float* W1,
                                                  const float* W2, const float* W3,
                                                  const float* W4, const float* W5) {
    int m = blockIdx.x;
    const float* src;
    switch (m) {
        case 0: src = W0; break;
        case 1: src = W1; break;
        case 2: src = W2; break;
        case 3: src = W3; break;
        case 4: src = W4; break;
        case 5: src = W5; break;
        default: src = g_WS + (size_t)(m - 6) * 16384; break;
    }
    uint32_t* dst = g_Bimg + (size_t)m * 16384;
    for (int i = threadIdx.x; i < 16384; i += 256) {
        int l2 = i & 63;
        int nt = (i >> 6) & 15;
        int kit = i >> 10;
        int lane = l2 >> 1, half = l2 & 1;
        int k = kit * 8 + (lane & 3) + half * 4;
        int n = nt * 8 + (lane >> 2);
        dst[i] = f2tf32(src[k * DHD + n]);
    }
}

// ---------------- tf32 tensor-core GEMM mainloop ----------------
__device__ __forceinline__ void gemm_mainloop(float (*acc)[8][4], uint32_t* sm,
                                              const float* __restrict__ Xp,
                                              const int* rows, int matIdx, int tid) {
    int lane = tid & 31, wid = tid >> 5;
    int warp_m = wid & 3, warp_n = wid >> 2;
    uint32_t* sAhi = sm;
    uint32_t* sAlo = sm + OFF_ALO;
    uint32_t* sB = sm + OFF_B;

    for (int kc = 0; kc < 2; kc++) {
        if (kc) __syncthreads();
#pragma unroll
        for (int it = 0; it < 8; it++) {
            int i = tid + it * 256;
            int row = i >> 4, f4 = i & 15;
            int gr = rows[row];
            float4 v = make_float4(0.f, 0.f, 0.f, 0.f);
            if (gr >= 0) v = *(const float4*)(Xp + (size_t)gr * DHD + kc * 64 + f4 * 4);
            int base = row * SA_STRIDE + f4 * 4;
            uint32_t h0, l0, h1, l1, h2, l2, h3, l3;
            split_tf32(v.x, h0, l0);
            split_tf32(v.y, h1, l1);
            split_tf32(v.z, h2, l2);
            split_tf32(v.w, h3, l3);
            *(uint4*)(sAhi + base) = make_uint4(h0, h1, h2, h3);
            *(uint4*)(sAlo + base) = make_uint4(l0, l1, l2, l3);
        }
        const uint4* bsrc = (const uint4*)(g_Bimg + (size_t)matIdx * 16384 + kc * 8192);
#pragma unroll
        for (int it = 0; it < 8; it++) {
            ((uint4*)sB)[tid + it * 256] = bsrc[tid + it * 256];
        }
        __syncthreads();

#pragma unroll
        for (int kit = 0; kit < 8; kit++) {
            uint32_t ah[2][4], al[2][4];
#pragma unroll
            for (int mt = 0; mt < 2; mt++) {
                int r0 = warp_m * 32 + mt * 16 + (lane >> 2);
                int kk = kit * 8 + (lane & 3);
                ah[mt][0] = sAhi[r0 * SA_STRIDE + kk];
                ah[mt][1] = sAhi[(r0 + 8) * SA_STRIDE + kk];
                ah[mt][2] = sAhi[r0 * SA_STRIDE + kk + 4];
                ah[mt][3] = sAhi[(r0 + 8) * SA_STRIDE + kk + 4];
                al[mt][0] = sAlo[r0 * SA_STRIDE + kk];
                al[mt][1] = sAlo[(r0 + 8) * SA_STRIDE + kk];
                al[mt][2] = sAlo[r0 * SA_STRIDE + kk + 4];
                al[mt][3] = sAlo[(r0 + 8) * SA_STRIDE + kk + 4];
            }
#pragma unroll
            for (int nt = 0; nt < 8; nt++) {
                int gnt = warp_n * 8 + nt;
                uint2 b = *(uint2*)(sB + (kit * 16 + gnt) * 64 + lane * 2);
#pragma unroll
                for (int mt = 0; mt < 2; mt++) {
                    mma8(acc[mt][nt], ah[mt], b);
                    mma8(acc[mt][nt], al[mt], b);
                }
            }
        }
    }
}

#define DECL_ACC(acc)                     \
    float acc[2][8][4];                   \
    _Pragma("unroll") for (int _a = 0; _a < 2; _a++) _Pragma("unroll") for (int _b = 0;        \
                                                                            _b < 8; _b++)      \
        _Pragma("unroll") for (int _c = 0; _c < 4; _c++) acc[_a][_b][_c] = 0.f;

// ---------------- fused Y GEMMs (bf16 output) ----------------
// mode 0: X -> g_yX [N,384], convs {0,2,4}, with bias
// mode 1: h -> g_yH [N,256], convs {1,3}
// mode 2: rh -> g_yHH [N,128], conv 5
__global__ void __launch_bounds__(256) gemm_y_f(const float* __restrict__ Aext, int mode,
                                                const float* __restrict__ bxz,
                                                const float* __restrict__ bxr,
                                                const float* __restrict__ bxh,
                                                const int* __restrict__ role) {
    extern __shared__ __align__(16) uint32_t sm[];
    __shared__ float sg[DHD * 3];
    __shared__ float bb[DHD * 3];
    __shared__ int role_s[DHD];
    __shared__ int rows[DHD];

    int tid = threadIdx.x, ct = blockIdx.y;
    int r0 = blockIdx.x * DHD;
    const float* Xp = Aext ? Aext : g_rh;

    int conv, ostride;
    __nv_bfloat16* obase;
    const float* bvec = nullptr;
    if (mode == 0) {
        conv = ct * 2;
        ostride = 384;
        obase = g_yX;
        bvec = (ct == 0) ? bxz : ((ct == 1) ? bxr : bxh);
    } else if (mode == 1) {
        conv = 1 + ct * 2;
        ostride = 256;
        obase = g_yH;
    } else {
        conv = 5;
        ostride = 128;
        obase = g_yHH;
    }

    for (int t = tid; t < 3 * DHD; t += 256) {
        sg[t] = g_gate[conv * 384 + t];
        bb[t] = bvec ? bvec[t] : 0.0f;
    }
    if (tid < DHD) {
        int gr = r0 + tid;
        rows[tid] = (gr < NN) ? gr : -1;
        role_s[tid] = (gr < NN) ? role[gr] : 0;
    }
    __syncthreads();

    DECL_ACC(acc)
    gemm_mainloop(acc, sm, Xp, rows, conv, tid);

    int lane = tid & 31, wid = tid >> 5;
    int warp_m = wid & 3, warp_n = wid >> 2;
#pragma unroll
    for (int mt = 0; mt < 2; mt++) {
#pragma unroll
        for (int h = 0; h < 2; h++) {
            int lrow = warp_m * 32 + mt * 16 + (lane >> 2) + h * 8;
            int grow = r0 + lrow;
            if (grow >= NN) continue;
            int rb = role_s[lrow] * 128;
            __nv_bfloat16* yp = obase + (size_t)grow * ostride + ct * 128;
#pragma unroll
            for (int nt = 0; nt < 8; nt++) {
                int col = warp_n * 64 + nt * 8 + (lane & 3) * 2;
                float v0 = acc[mt][nt][h * 2] * sg[rb + col] + bb[rb + col];
                float v1 = acc[mt][nt][h * 2 + 1] * sg[rb + col + 1] + bb[rb + col + 1];
                *(__nv_bfloat162*)(yp + col) = __float22bfloat162_rn(make_float2(v0, v1));
            }
        }
    }
}

// ---------------- fused self GEMMs: buf2 = A[node] @ WS[conv][role] (overwrite) -----
__global__ void __launch_bounds__(256) gemm_self_f(const float* __restrict__ Aext, int mode) {
    int rowBase = blockIdx.x * DHD;
    if (rowBase >= g_rolePadOff[3]) return;
    extern __shared__ __align__(16) uint32_t sm[];
    __shared__ int rows[DHD];

    int tid = threadIdx.x, ct = blockIdx.y;
    const float* Xp = Aext ? Aext : g_rh;

    int r = 0;
    if (rowBase >= g_rolePadOff[1]) r = 1;
    if (rowBase >= g_rolePadOff[2]) r = 2;

    int conv, ostride;
    float* obase;
    if (mode == 0) { conv = ct * 2; ostride = 384; obase = g_bufX2; }
    else if (mode == 1) { conv = 1 + ct * 2; ostride = 256; obase = g_bufH2; }
    else { conv = 5; ostride = 128; obase = g_bufHH2; }
    int matIdx = 6 + conv * 3 + r;

    if (tid < DHD) rows[tid] = (rowBase + tid < PERM_SZ) ? g_perm[rowBase + tid] : -1;
    __syncthreads();

    DECL_ACC(acc)
    gemm_mainloop(acc, sm, Xp, rows, matIdx, tid);

    int lane = tid & 31, wid = tid >> 5;
    int warp_m = wid & 3, warp_n = wid >> 2;
#pragma unroll
    for (int mt = 0; mt < 2; mt++) {
#pragma unroll
        for (int h = 0; h < 2; h++) {
            int lrow = warp_m * 32 + mt * 16 + (lane >> 2) + h * 8;
            int node = rows[lrow];
            if (node < 0) continue;
            float* cp = obase + (size_t)node * ostride + ct * 128;
#pragma unroll
            for (int nt = 0; nt < 8; nt++) {
                int col = warp_n * 64 + nt * 8 + (lane & 3) * 2;
                *(float2*)(cp + col) =
                    make_float2(acc[mt][nt][h * 2], acc[mt][nt][h * 2 + 1]);
            }
        }
    }
}

// ---------------- fused gathers (warp per node) ----------------
__device__ __forceinline__ void bfacc(float4& a, uint2 u) {
    float2 f0 = __bfloat1622float2(*(__nv_bfloat162*)&u.x);
    float2 f1 = __bfloat1622float2(*(__nv_bfloat162*)&u.y);
    a.x += f0.x; a.y += f0.y; a.z += f1.x; a.w += f1.y;
}
__device__ __forceinline__ float4 scale4(float4 a, float s) {
    return make_float4(a.x * s, a.y * s, a.z * s, a.w * s);
}

// combined gather over yX (3 segs) and yH (2 segs)
__global__ void __launch_bounds__(256) gather_xh_kernel() {
    int w = (blockIdx.x * blockDim.x + threadIdx.x) >> 5;
    int lane = threadIdx.x & 31;
    if (w >= NN) return;
    int s = g_off[w], e = g_off[w + 1];
    float4 a[5];
#pragma unroll
    for (int q = 0; q < 5; q++) a[q] = make_float4(0.f, 0.f, 0.f, 0.f);
    for (int p = s; p < e; p++) {
        int s0 = g_csr[p];
        const uint2* bx = (const uint2*)(g_yX + (size_t)s0 * 384);
        const uint2* bh = (const uint2*)(g_yH + (size_t)s0 * 256);
        uint2 u[5];
#pragma unroll
        for (int q = 0; q < 3; q++) u[q] = bx[lane + q * 32];
#pragma unroll
        for (int q = 0; q < 2; q++) u[3 + q] = bh[lane + q * 32];
#pragma unroll
        for (int q = 0; q < 5; q++) bfacc(a[q], u[q]);
    }
    float inv = 1.0f / (float)(e - s);
    float* ox = g_bufX + (size_t)w * 384;
    float* oh = g_bufH + (size_t)w * 256;
#pragma unroll
    for (int q = 0; q < 3; q++) *(float4*)(ox + q * 128 + lane * 4) = scale4(a[q], inv);
#pragma unroll
    for (int q = 0; q < 2; q++) *(float4*)(oh + q * 128 + lane * 4) = scale4(a[3 + q], inv);
}

__global__ void __launch_bounds__(256) gather_hh_kernel() {
    int w = (blockIdx.x * blockDim.x + threadIdx.x) >> 5;
    int lane = threadIdx.x & 31;
    if (w >= NN) return;
    int s = g_off[w], e = g_off[w + 1];
    float4 a0 = make_float4(0.f, 0.f, 0.f, 0.f);
    float4 a1 = make_float4(0.f, 0.f, 0.f, 0.f);
    int p = s;
    for (; p + 2 <= e; p += 2) {
        int s0 = g_csr[p], s1 = g_csr[p + 1];
        uint2 u0 = ((const uint2*)(g_yHH + (size_t)s0 * 128))[lane];
        uint2 u1 = ((const uint2*)(g_yHH + (size_t)s1 * 128))[lane];
        bfacc(a0, u0);
        bfacc(a1, u1);
    }
    if (p < e) {
        uint2 u0 = ((const uint2*)(g_yHH + (size_t)g_csr[p] * 128))[lane];
        bfacc(a0, u0);
    }
    float inv = 1.0f / (float)(e - s);
    a0.x += a1.x; a0.y += a1.y; a0.z += a1.z; a0.w += a1.w;
    *(float4*)(g_bufHH + (size_t)w * 128 + lane * 4) = scale4(a0, inv);
}

// ---------------- combines ----------------
__device__ __forceinline__ float sigm(float x) { return 1.0f / (1.0f + __expf(-x)); }
__device__ __forceinline__ float rl(float x) { return fmaxf(x, 0.f); }

__global__ void combine_zr_kernel(const float* __restrict__ h) {
    size_t idx = (size_t)blockIdx.x * blockDim.x + threadIdx.x;
    if (idx >= (size_t)NN * 32) return;
    size_t i = idx >> 5;
    int q = (int)(idx & 31);
    float4 xz = *(const float4*)(g_bufX + i * 384 + q * 4);
    float4 xz2 = *(const float4*)(g_bufX2 + i * 384 + q * 4);
    float4 xr = *(const float4*)(g_bufX + i * 384 + 128 + q * 4);
    float4 xr2 = *(const float4*)(g_bufX2 + i * 384 + 128 + q * 4);
    float4 hz = *(const float4*)(g_bufH + i * 256 + q * 4);
    float4 hz2 = *(const float4*)(g_bufH2 + i * 256 + q * 4);
    float4 hr = *(const float4*)(g_bufH + i * 256 + 128 + q * 4);
    float4 hr2 = *(const float4*)(g_bufH2 + i * 256 + 128 + q * 4);
    float4 hv = *(const float4*)(h + i * 128 + q * 4);
    float4 z, rr;
    z.x = sigm(rl(xz.x + xz2.x) + rl(hz.x + hz2.x));
    z.y = sigm(rl(xz.y + xz2.y) + rl(hz.y + hz2.y));
    z.z = sigm(rl(xz.z + xz2.z) + rl(hz.z + hz2.z));
    z.w = sigm(rl(xz.w + xz2.w) + rl(hz.w + hz2.w));
    rr.x = sigm(rl(xr.x + xr2.x) + rl(hr.x + hr2.x)) * hv.x;
    rr.y = sigm(rl(xr.y + xr2.y) + rl(hr.y + hr2.y)) * hv.y;
    rr.z = sigm(rl(xr.z + xr2.z) + rl(hr.z + hr2.z)) * hv.z;
    rr.w = sigm(rl(xr.w + xr2.w) + rl(hr.w + hr2.w)) * hv.w;
    *(float4*)(g_z + i * 128 + q * 4) = z;
    *(float4*)(g_rh + i * 128 + q * 4) = rr;
}

__global__ void combine_h_kernel(const float* __restrict__ h, float* __restrict__ out) {
    size_t idx = (size_t)blockIdx.x * blockDim.x + threadIdx.x;
    if (idx >= (size_t)NN * 32) return;
    size_t i = idx >> 5;
    int q = (int)(idx & 31);
    float4 xh = *(const float4*)(g_bufX + i * 384 + 256 + q * 4);
    float4 xh2 = *(const float4*)(g_bufX2 + i * 384 + 256 + q * 4);
    float4 hh = *(const float4*)(g_bufHH + i * 128 + q * 4);
    float4 hh2 = *(const float4*)(g_bufHH2 + i * 128 + q * 4);
    float4 zv = *(const float4*)(g_z + i * 128 + q * 4);
    float4 hv = *(const float4*)(h + i * 128 + q * 4);
    float4 o;
    float t;
    t = tanhf(rl(xh.x + xh2.x) + rl(hh.x + hh2.x)); o.x = zv.x * hv.x + (1.f - zv.x) * t;
    t = tanhf(rl(xh.y + xh2.y) + rl(hh.y + hh2.y)); o.y = zv.y * hv.y + (1.f - zv.y) * t;
    t = tanhf(rl(xh.z + xh2.z) + rl(hh.z + hh2.z)); o.z = zv.z * hv.z + (1.f - zv.z) * t;
    t = tanhf(rl(xh.w + xh2.w) + rl(hh.w + hh2.w)); o.w = zv.w * hv.w + (1.f - zv.w) * t;
    *(float4*)(out + i * 128 + q * 4) = o;
}

// ---------------- host launch ----------------
extern "C" void kernel_launch(void* const* d_in, const int* in_sizes, int n_in,
                              void* d_out, int out_size) {
    cudaFuncSetAttribute(gemm_y_f, cudaFuncAttributeMaxDynamicSharedMemorySize, GEMM_SMEM);
    cudaFuncSetAttribute(gemm_self_f, cudaFuncAttributeMaxDynamicSharedMemorySize, GEMM_SMEM);

    // Side stream + events for fork-join graph parallelism (created once; reused).
    static cudaStream_t s1 = nullptr;
    static cudaEvent_t evF = nullptr, evA = nullptr, evB = nullptr, evC = nullptr,
                       evD = nullptr, evE = nullptr;
    if (!s1) {
        cudaStreamCreateWithFlags(&s1, cudaStreamNonBlocking);
        cudaEventCreateWithFlags(&evF, cudaEventDisableTiming);
        cudaEventCreateWithFlags(&evA, cudaEventDisableTiming);
        cudaEventCreateWithFlags(&evB, cudaEventDisableTiming);
        cudaEventCreateWithFlags(&evC, cudaEventDisableTiming);
        cudaEventCreateWithFlags(&evD, cudaEventDisableTiming);
        cudaEventCreateWithFlags(&evE, cudaEventDisableTiming);
    }

    int iEdge = 2, iH = 1;
    if (in_sizes[1] == 2 * EE) { iEdge = 1; iH = 2; }
    const float* x = (const float*)d_in[0];
    const float* h_prev = (const float*)d_in[iH];
    const int* ei = (const int*)d_in[iEdge];
    const int* role = (const int*)d_in[3];

    const float* P[27];
    for (int i = 0; i < 27 && (4 + i) < n_in; i++) P[i] = (const float*)d_in[4 + i];
    // xz: W,Wg,bg,S,b = P0..P4 | hz: P5..P8 | xr: P9..P13 | hr: P14..P17
    // xh: P18..P22 | hh: P23..P26
    float* out = (float*)d_out;

    int warpGrid = (NN * 32 + 255) / 256;

    // ---- Fork 1: CSR build (s1) || weight prep + Y GEMMs (main) ----
    cudaEventRecord(evF, 0);
    cudaStreamWaitEvent(s1, evF, 0);
    init_kernel<<<(PERM_SZ + 255) / 256, 256, 0, s1>>>();
    count_kernel<<<(ET + 255) / 256, 256, 0, s1>>>(ei, role);
    scan_kernel<<<1, 1024, 0, s1>>>();
    fill_kernel<<<(ET + 255) / 256, 256, 0, s1>>>(ei, role);
    cudaEventRecord(evA, s1);

    gates_kernel<<<6, 384>>>(P[1], P[2], P[6], P[7], P[10], P[11], P[15], P[16], P[19], P[20],
                             P[24], P[25]);
    ws_all_kernel<<<dim3(4, 3, 6), 256>>>(P[0], P[3], P[5], P[8], P[9], P[12], P[14], P[17],
                                          P[18], P[21], P[23], P[26]);
    img_kernel<<<24, 256>>>(P[0], P[5], P[9], P[14], P[18], P[23]);
    gemm_y_f<<<dim3(RB, 3), 256, GEMM_SMEM>>>(x, 0, P[4], P[13], P[22], role);
    gemm_y_f<<<dim3(RB, 2), 256, GEMM_SMEM>>>(h_prev, 1, nullptr, nullptr, nullptr, role);
    cudaStreamWaitEvent(0, evA, 0);  // join: CSR ready

    // ---- Fork 2: gathers (main, L2-bound) || self GEMMs (s1, tensor-bound) ----
    cudaEventRecord(evB, 0);
    cudaStreamWaitEvent(s1, evB, 0);
    gemm_self_f<<<dim3(SB, 3), 256, GEMM_SMEM, s1>>>(x, 0);
    gemm_self_f<<<dim3(SB, 2), 256, GEMM_SMEM, s1>>>(h_prev, 1);
    cudaEventRecord(evC, s1);
    gather_xh_kernel<<<warpGrid, 256>>>();
    cudaStreamWaitEvent(0, evC, 0);  // join

    combine_zr_kernel<<<warpGrid, 256>>>(h_prev);

    // ---- Fork 3: self_hh (s1) || yHH -> gather_hh (main) ----
    cudaEventRecord(evD, 0);
    cudaStreamWaitEvent(s1, evD, 0);
    gemm_self_f<<<dim3(SB, 1), 256, GEMM_SMEM, s1>>>(nullptr, 2);
    cudaEventRecord(evE, s1);
    gemm_y_f<<<dim3(RB, 1), 256, GEMM_SMEM>>>(nullptr, 2, nullptr, nullptr, nullptr, role);
    gather_hh_kernel<<<warpGrid, 256>>>();
    cudaStreamWaitEvent(0, evE, 0);  // join

    combine_h_kernel<<<warpGrid, 256>>>(h_prev, out);
}

// round 12
// speedup vs baseline: 1.9507x; 1.1819x over previous
#include <cuda_runtime.h>
#include <cuda_bf16.h>
#include <cstdint>

// Problem constants
#define NN 50000
#define EE 1600000
#define ET (EE + NN)
#define DHD 128
#define PERM_SZ (NN + 3 * 128)
#define RB ((NN + 127) / 128)       // 391
#define SB ((PERM_SZ + 127) / 128)  // 396

// Dynamic smem (words): A[128][68] | Bfrag chunk [8][16][64]
#define SA_STRIDE 68
#define OFF_B (128 * SA_STRIDE)
#define GEMM_SMEM ((128 * SA_STRIDE + 8 * 16 * 64) * 4)  // 67584 B

// ---------------- device scratch ----------------
__device__ __nv_bfloat16 g_yX[(size_t)NN * 384];   // gated X-side messages (xz|xr|xh)
__device__ __nv_bfloat16 g_yH[(size_t)NN * 256];   // gated h-side messages (hz|hr)
__device__ __nv_bfloat16 g_yHH[(size_t)NN * 128];  // gated rh messages (hh)
__device__ float g_bufX[(size_t)NN * 384];   // gather results
__device__ float g_bufH[(size_t)NN * 256];
__device__ float g_bufHH[(size_t)NN * 128];
__device__ float g_bufX2[(size_t)NN * 384];  // self-GEMM results (separate: enables overlap)
__device__ float g_bufH2[(size_t)NN * 256];
__device__ float g_bufHH2[(size_t)NN * 128];
__device__ float g_z[(size_t)NN * DHD];
__device__ float g_rh[(size_t)NN * DHD];
__device__ float g_WS[18 * DHD * DHD];       // per-conv per-role W@S (plain [k][n])
__device__ float g_gate[6 * 3 * DHD];        // sigmoid(Wg+bg) per conv/role
__device__ uint32_t g_Bimg[24 * DHD * DHD];  // tf32 fragment-ordered B images
__device__ int g_deg[NN];
__device__ int g_off[NN + 1];
__device__ int g_pos[NN];
__device__ int g_csr[ET];
__device__ int g_roleCnt[3];
__device__ int g_rolePadOff[4];
__device__ int g_rolePos[3];
__device__ int g_perm[PERM_SZ];

// ---------------- tf32 helpers ----------------
__device__ __forceinline__ uint32_t f2tf32(float x) {
    uint32_t r;
    asm("cvt.rna.tf32.f32 %0, %1;" : "=r"(r) : "f"(x));
    return r;
}
__device__ __forceinline__ void mma8(float* c, const uint32_t* a, uint2 b) {
    asm volatile(
        "mma.sync.aligned.m16n8k8.row.col.f32.tf32.tf32.f32 "
        "{%0,%1,%2,%3},{%4,%5,%6,%7},{%8,%9},{%0,%1,%2,%3};"
        : "+f"(c[0]), "+f"(c[1]), "+f"(c[2]), "+f"(c[3])
        : "r"(a[0]), "r"(a[1]), "r"(a[2]), "r"(a[3]), "r"(b.x), "r"(b.y));
}

// ---------------- preprocessing ----------------
__global__ void init_kernel() {
    int i = blockIdx.x * blockDim.x + threadIdx.x;
    if (i < NN) g_deg[i] = 0;
    if (i < 3) g_roleCnt[i] = 0;
    if (i < PERM_SZ) g_perm[i] = -1;
}

__global__ void count_kernel(const int* __restrict__ ei, const int* __restrict__ role) {
    int e = blockIdx.x * blockDim.x + threadIdx.x;
    if (e < ET) {
        int c = (e < EE) ? ei[EE + e] : (e - EE);
        atomicAdd(&g_deg[c], 1);
    }
    if (e < NN) atomicAdd(&g_roleCnt[role[e]], 1);
}

__global__ void scan_kernel() {
    __shared__ int warpsum[32];
    __shared__ int s_tot;
    __shared__ int s_carry;
    int t = threadIdx.x, lane = t & 31, w = t >> 5;
    if (t == 0) s_carry = 0;
    __syncthreads();
    for (int base = 0; base < NN; base += 1024) {
        int v = (base + t < NN) ? g_deg[base + t] : 0;
        int s = v;
#pragma unroll
        for (int o = 1; o < 32; o <<= 1) {
            int n = __shfl_up_sync(~0u, s, o);
            if (lane >= o) s += n;
        }
        if (lane == 31) warpsum[w] = s;
        __syncthreads();
        if (w == 0) {
            int ws = warpsum[lane];
            int t2 = ws;
#pragma unroll
            for (int o = 1; o < 32; o <<= 1) {
                int n = __shfl_up_sync(~0u, t2, o);
                if (lane >= o) t2 += n;
            }
            warpsum[lane] = t2 - ws;
            if (lane == 31) s_tot = t2;
        }
        __syncthreads();
        int excl = s_carry + warpsum[w] + s - v;
        if (base + t < NN) {
            g_off[base + t] = excl;
            g_pos[base + t] = excl;
        }
        __syncthreads();
        if (t == 0) s_carry += s_tot;
        __syncthreads();
    }
    if (t == 0) {
        g_off[NN] = s_carry;
        int o = 0;
        for (int r2 = 0; r2 < 3; r2++) {
            g_rolePadOff[r2] = o;
            g_rolePos[r2] = o;
            o += ((g_roleCnt[r2] + 127) >> 7) << 7;
        }
        g_rolePadOff[3] = o;
    }
}

__global__ void fill_kernel(const int* __restrict__ ei, const int* __restrict__ role) {
    int e = blockIdx.x * blockDim.x + threadIdx.x;
    if (e < ET) {
        int r, c;
        if (e < EE) { r = ei[e]; c = ei[EE + e]; }
        else { r = e - EE; c = e - EE; }
        int p = atomicAdd(&g_pos[c], 1);
        g_csr[p] = r;
    }
    if (e < NN) {
        int q = atomicAdd(&g_rolePos[role[e]], 1);
        g_perm[q] = e;
    }
}

// gates: sigmoid(Wg + bg) for all 6 convs (order: xz,hz,xr,hr,xh,hh)
__global__ void gates_kernel(const float* g0, const float* b0, const float* g1, const float* b1,
                             const float* g2, const float* b2, const float* g3, const float* b3,
                             const float* g4, const float* b4, const float* g5, const float* b5) {
    int c = blockIdx.x, t = threadIdx.x;
    const float* gp;
    const float* bp;
    switch (c) {
        case 0: gp = g0; bp = b0; break;
        case 1: gp = g1; bp = b1; break;
        case 2: gp = g2; bp = b2; break;
        case 3: gp = g3; bp = b3; break;
        case 4: gp = g4; bp = b4; break;
        default: gp = g5; bp = b5; break;
    }
    float v = gp[t] + bp[t];
    g_gate[c * 384 + t] = 1.0f / (1.0f + __expf(-v));
}

// ---------------- WS[conv][r] = W @ S[r] (fp32 exact, tiny) ----------------
__global__ void __launch_bounds__(256) ws_all_kernel(
    const float* W0, const float* S0, const float* W1, const float* S1,
    const float* W2, const float* S2, const float* W3, const float* S3,
    const float* W4, const float* S4, const float* W5, const float* S5) {
    int conv = blockIdx.z, r = blockIdx.y, ct = blockIdx.x;
    const float* W;
    const float* S;
    switch (conv) {
        case 0: W = W0; S = S0; break;
        case 1: W = W1; S = S1; break;
        case 2: W = W2; S = S2; break;
        case 3: W = W3; S = S3; break;
        case 4: W = W4; S = S4; break;
        default: W = W5; S = S5; break;
    }
    const float* B = S + ((size_t)r << 14) + ct * 32;
    float* C = g_WS + (((size_t)conv * 3 + r) << 14) + ct * 32;

    __shared__ float As[DHD][33];
    __shared__ float Bs[32][33];
    int tid = threadIdx.x;
    int tr = tid >> 4, tc = tid & 15;
    float acc[8][2] = {};
    for (int kc = 0; kc < DHD; kc += 32) {
#pragma unroll
        for (int t = 0; t < 4; t++) {
            int idx = tid + t * 256;
            int row = idx >> 3;
            int kq = (idx & 7) << 2;
            float4 v = *(const float4*)&W[(size_t)row * DHD + kc + kq];
            As[row][kq] = v.x; As[row][kq + 1] = v.y; As[row][kq + 2] = v.z; As[row][kq + 3] = v.w;
        }
#pragma unroll
        for (int t = 0; t < 4; t++) {
            int idx = tid + t * 256;
            int kk = idx >> 5;
            int j = idx & 31;
            Bs[kk][j] = B[(size_t)(kc + kk) * DHD + j];
        }
        __syncthreads();
#pragma unroll 8
        for (int kk = 0; kk < 32; kk++) {
            float b0 = Bs[kk][tc * 2], b1 = Bs[kk][tc * 2 + 1];
#pragma unroll
            for (int i = 0; i < 8; i++) {
                float a = As[tr * 8 + i][kk];
                acc[i][0] += a * b0;
                acc[i][1] += a * b1;
            }
        }
        __syncthreads();
    }
#pragma unroll
    for (int i = 0; i < 8; i++) {
        C[(size_t)(tr * 8 + i) * DHD + tc * 2] = acc[i][0];
        C[(size_t)(tr * 8 + i) * DHD + tc * 2 + 1] = acc[i][1];
    }
}

// ---------------- build tf32 fragment-ordered B images ----------------
__global__ void __launch_bounds__(256) img_kernel(const float* W0, const float* W1,
                                                  const float* W2, const float* W3,
                                                  const float* W4, const float* W5) {
    int m = blockIdx.x;
    const float* src;
    switch (m) {
        case 0: src = W0; break;
        case 1: src = W1; break;
        case 2: src = W2; break;
        case 3: src = W3; break;
        case 4: src = W4; break;
        case 5: src = W5; break;
        default: src = g_WS + (size_t)(m - 6) * 16384; break;
    }
    uint32_t* dst = g_Bimg + (size_t)m * 16384;
    for (int i = threadIdx.x; i < 16384; i += 256) {
        int l2 = i & 63;
        int nt = (i >> 6) & 15;
        int kit = i >> 10;
        int lane = l2 >> 1, half = l2 & 1;
        int k = kit * 8 + (lane & 3) + half * 4;
        int n = nt * 8 + (lane >> 2);
        dst[i] = f2tf32(src[k * DHD + n]);
    }
}

// ---------------- tf32 tensor-core GEMM mainloop (single-pass A) ----------------
__device__ __forceinline__ void gemm_mainloop(float (*acc)[8][4], uint32_t* sm,
                                              const float* __restrict__ Xp,
                                              const int* rows, int matIdx, int tid) {
    int lane = tid & 31, wid = tid >> 5;
    int warp_m = wid & 3, warp_n = wid >> 2;
    uint32_t* sA = sm;
    uint32_t* sB = sm + OFF_B;

    for (int kc = 0; kc < 2; kc++) {
        if (kc) __syncthreads();
#pragma unroll
        for (int it = 0; it < 8; it++) {
            int i = tid + it * 256;
            int row = i >> 4, f4 = i & 15;
            int gr = rows[row];
            float4 v = make_float4(0.f, 0.f, 0.f, 0.f);
            if (gr >= 0) v = *(const float4*)(Xp + (size_t)gr * DHD + kc * 64 + f4 * 4);
            int base = row * SA_STRIDE + f4 * 4;
            *(uint4*)(sA + base) = make_uint4(f2tf32(v.x), f2tf32(v.y), f2tf32(v.z), f2tf32(v.w));
        }
        const uint4* bsrc = (const uint4*)(g_Bimg + (size_t)matIdx * 16384 + kc * 8192);
#pragma unroll
        for (int it = 0; it < 8; it++) {
            ((uint4*)sB)[tid + it * 256] = bsrc[tid + it * 256];
        }
        __syncthreads();

#pragma unroll
        for (int kit = 0; kit < 8; kit++) {
            uint32_t ah[2][4];
#pragma unroll
            for (int mt = 0; mt < 2; mt++) {
                int r0 = warp_m * 32 + mt * 16 + (lane >> 2);
                int kk = kit * 8 + (lane & 3);
                ah[mt][0] = sA[r0 * SA_STRIDE + kk];
                ah[mt][1] = sA[(r0 + 8) * SA_STRIDE + kk];
                ah[mt][2] = sA[r0 * SA_STRIDE + kk + 4];
                ah[mt][3] = sA[(r0 + 8) * SA_STRIDE + kk + 4];
            }
#pragma unroll
            for (int nt = 0; nt < 8; nt++) {
                int gnt = warp_n * 8 + nt;
                uint2 b = *(uint2*)(sB + (kit * 16 + gnt) * 64 + lane * 2);
#pragma unroll
                for (int mt = 0; mt < 2; mt++) {
                    mma8(acc[mt][nt], ah[mt], b);
                }
            }
        }
    }
}

#define DECL_ACC(acc)                     \
    float acc[2][8][4];                   \
    _Pragma("unroll") for (int _a = 0; _a < 2; _a++) _Pragma("unroll") for (int _b = 0;        \
                                                                            _b < 8; _b++)      \
        _Pragma("unroll") for (int _c = 0; _c < 4; _c++) acc[_a][_b][_c] = 0.f;

// ---------------- fused Y GEMMs (bf16 output) ----------------
// mode 0: X -> g_yX [N,384], convs {0,2,4}, with bias
// mode 1: h -> g_yH [N,256], convs {1,3}
// mode 2: rh -> g_yHH [N,128], conv 5
__global__ void __launch_bounds__(256) gemm_y_f(const float* __restrict__ Aext, int mode,
                                                const float* __restrict__ bxz,
                                                const float* __restrict__ bxr,
                                                const float* __restrict__ bxh,
                                                const int* __restrict__ role) {
    extern __shared__ __align__(16) uint32_t sm[];
    __shared__ float sg[DHD * 3];
    __shared__ float bb[DHD * 3];
    __shared__ int role_s[DHD];
    __shared__ int rows[DHD];

    int tid = threadIdx.x, ct = blockIdx.y;
    int r0 = blockIdx.x * DHD;
    const float* Xp = Aext ? Aext : g_rh;

    int conv, ostride;
    __nv_bfloat16* obase;
    const float* bvec = nullptr;
    if (mode == 0) {
        conv = ct * 2;
        ostride = 384;
        obase = g_yX;
        bvec = (ct == 0) ? bxz : ((ct == 1) ? bxr : bxh);
    } else if (mode == 1) {
        conv = 1 + ct * 2;
        ostride = 256;
        obase = g_yH;
    } else {
        conv = 5;
        ostride = 128;
        obase = g_yHH;
    }

    for (int t = tid; t < 3 * DHD; t += 256) {
        sg[t] = g_gate[conv * 384 + t];
        bb[t] = bvec ? bvec[t] : 0.0f;
    }
    if (tid < DHD) {
        int gr = r0 + tid;
        rows[tid] = (gr < NN) ? gr : -1;
        role_s[tid] = (gr < NN) ? role[gr] : 0;
    }
    __syncthreads();

    DECL_ACC(acc)
    gemm_mainloop(acc, sm, Xp, rows, conv, tid);

    int lane = tid & 31, wid = tid >> 5;
    int warp_m = wid & 3, warp_n = wid >> 2;
#pragma unroll
    for (int mt = 0; mt < 2; mt++) {
#pragma unroll
        for (int h = 0; h < 2; h++) {
            int lrow = warp_m * 32 + mt * 16 + (lane >> 2) + h * 8;
            int grow = r0 + lrow;
            if (grow >= NN) continue;
            int rb = role_s[lrow] * 128;
            __nv_bfloat16* yp = obase + (size_t)grow * ostride + ct * 128;
#pragma unroll
            for (int nt = 0; nt < 8; nt++) {
                int col = warp_n * 64 + nt * 8 + (lane & 3) * 2;
                float v0 = acc[mt][nt][h * 2] * sg[rb + col] + bb[rb + col];
                float v1 = acc[mt][nt][h * 2 + 1] * sg[rb + col + 1] + bb[rb + col + 1];
                *(__nv_bfloat162*)(yp + col) = __float22bfloat162_rn(make_float2(v0, v1));
            }
        }
    }
}

// ---------------- fused self GEMMs: buf2 = A[node] @ WS[conv][role] (overwrite) -----
__global__ void __launch_bounds__(256) gemm_self_f(const float* __restrict__ Aext, int mode) {
    int rowBase = blockIdx.x * DHD;
    if (rowBase >= g_rolePadOff[3]) return;
    extern __shared__ __align__(16) uint32_t sm[];
    __shared__ int rows[DHD];

    int tid = threadIdx.x, ct = blockIdx.y;
    const float* Xp = Aext ? Aext : g_rh;

    int r = 0;
    if (rowBase >= g_rolePadOff[1]) r = 1;
    if (rowBase >= g_rolePadOff[2]) r = 2;

    int conv, ostride;
    float* obase;
    if (mode == 0) { conv = ct * 2; ostride = 384; obase = g_bufX2; }
    else if (mode == 1) { conv = 1 + ct * 2; ostride = 256; obase = g_bufH2; }
    else { conv = 5; ostride = 128; obase = g_bufHH2; }
    int matIdx = 6 + conv * 3 + r;

    if (tid < DHD) rows[tid] = (rowBase + tid < PERM_SZ) ? g_perm[rowBase + tid] : -1;
    __syncthreads();

    DECL_ACC(acc)
    gemm_mainloop(acc, sm, Xp, rows, matIdx, tid);

    int lane = tid & 31, wid = tid >> 5;
    int warp_m = wid & 3, warp_n = wid >> 2;
#pragma unroll
    for (int mt = 0; mt < 2; mt++) {
#pragma unroll
        for (int h = 0; h < 2; h++) {
            int lrow = warp_m * 32 + mt * 16 + (lane >> 2) + h * 8;
            int node = rows[lrow];
            if (node < 0) continue;
            float* cp = obase + (size_t)node * ostride + ct * 128;
#pragma unroll
            for (int nt = 0; nt < 8; nt++) {
                int col = warp_n * 64 + nt * 8 + (lane & 3) * 2;
                *(float2*)(cp + col) =
                    make_float2(acc[mt][nt][h * 2], acc[mt][nt][h * 2 + 1]);
            }
        }
    }
}

// ---------------- fused gathers (warp per node) ----------------
__device__ __forceinline__ void bfacc(float4& a, uint2 u) {
    float2 f0 = __bfloat1622float2(*(__nv_bfloat162*)&u.x);
    float2 f1 = __bfloat1622float2(*(__nv_bfloat162*)&u.y);
    a.x += f0.x; a.y += f0.y; a.z += f1.x; a.w += f1.y;
}
__device__ __forceinline__ float4 scale4(float4 a, float s) {
    return make_float4(a.x * s, a.y * s, a.z * s, a.w * s);
}

// combined gather over yX (3 segs) and yH (2 segs)
__global__ void __launch_bounds__(256) gather_xh_kernel() {
    int w = (blockIdx.x * blockDim.x + threadIdx.x) >> 5;
    int lane = threadIdx.x & 31;
    if (w >= NN) return;
    int s = g_off[w], e = g_off[w + 1];
    float4 a[5];
#pragma unroll
    for (int q = 0; q < 5; q++) a[q] = make_float4(0.f, 0.f, 0.f, 0.f);
    for (int p = s; p < e; p++) {
        int s0 = g_csr[p];
        const uint2* bx = (const uint2*)(g_yX + (size_t)s0 * 384);
        const uint2* bh = (const uint2*)(g_yH + (size_t)s0 * 256);
        uint2 u[5];
#pragma unroll
        for (int q = 0; q < 3; q++) u[q] = bx[lane + q * 32];
#pragma unroll
        for (int q = 0; q < 2; q++) u[3 + q] = bh[lane + q * 32];
#pragma unroll
        for (int q = 0; q < 5; q++) bfacc(a[q], u[q]);
    }
    float inv = 1.0f / (float)(e - s);
    float* ox = g_bufX + (size_t)w * 384;
    float* oh = g_bufH + (size_t)w * 256;
#pragma unroll
    for (int q = 0; q < 3; q++) *(float4*)(ox + q * 128 + lane * 4) = scale4(a[q], inv);
#pragma unroll
    for (int q = 0; q < 2; q++) *(float4*)(oh + q * 128 + lane * 4) = scale4(a[3 + q], inv);
}

__global__ void __launch_bounds__(256) gather_hh_kernel() {
    int w = (blockIdx.x * blockDim.x + threadIdx.x) >> 5;
    int lane = threadIdx.x & 31;
    if (w >= NN) return;
    int s = g_off[w], e = g_off[w + 1];
    float4 a0 = make_float4(0.f, 0.f, 0.f, 0.f);
    float4 a1 = make_float4(0.f, 0.f, 0.f, 0.f);
    int p = s;
    for (; p + 2 <= e; p += 2) {
        int s0 = g_csr[p], s1 = g_csr[p + 1];
        uint2 u0 = ((const uint2*)(g_yHH + (size_t)s0 * 128))[lane];
        uint2 u1 = ((const uint2*)(g_yHH + (size_t)s1 * 128))[lane];
        bfacc(a0, u0);
        bfacc(a1, u1);
    }
    if (p < e) {
        uint2 u0 = ((const uint2*)(g_yHH + (size_t)g_csr[p] * 128))[lane];
        bfacc(a0, u0);
    }
    float inv = 1.0f / (float)(e - s);
    a0.x += a1.x; a0.y += a1.y; a0.z += a1.z; a0.w += a1.w;
    *(float4*)(g_bufHH + (size_t)w * 128 + lane * 4) = scale4(a0, inv);
}

// ---------------- combines ----------------
__device__ __forceinline__ float sigm(float x) { return 1.0f / (1.0f + __expf(-x)); }
__device__ __forceinline__ float rl(float x) { return fmaxf(x, 0.f); }

__global__ void combine_zr_kernel(const float* __restrict__ h) {
    size_t idx = (size_t)blockIdx.x * blockDim.x + threadIdx.x;
    if (idx >= (size_t)NN * 32) return;
    size_t i = idx >> 5;
    int q = (int)(idx & 31);
    float4 xz = *(const float4*)(g_bufX + i * 384 + q * 4);
    float4 xz2 = *(const float4*)(g_bufX2 + i * 384 + q * 4);
    float4 xr = *(const float4*)(g_bufX + i * 384 + 128 + q * 4);
    float4 xr2 = *(const float4*)(g_bufX2 + i * 384 + 128 + q * 4);
    float4 hz = *(const float4*)(g_bufH + i * 256 + q * 4);
    float4 hz2 = *(const float4*)(g_bufH2 + i * 256 + q * 4);
    float4 hr = *(const float4*)(g_bufH + i * 256 + 128 + q * 4);
    float4 hr2 = *(const float4*)(g_bufH2 + i * 256 + 128 + q * 4);
    float4 hv = *(const float4*)(h + i * 128 + q * 4);
    float4 z, rr;
    z.x = sigm(rl(xz.x + xz2.x) + rl(hz.x + hz2.x));
    z.y = sigm(rl(xz.y + xz2.y) + rl(hz.y + hz2.y));
    z.z = sigm(rl(xz.z + xz2.z) + rl(hz.z + hz2.z));
    z.w = sigm(rl(xz.w + xz2.w) + rl(hz.w + hz2.w));
    rr.x = sigm(rl(xr.x + xr2.x) + rl(hr.x + hr2.x)) * hv.x;
    rr.y = sigm(rl(xr.y + xr2.y) + rl(hr.y + hr2.y)) * hv.y;
    rr.z = sigm(rl(xr.z + xr2.z) + rl(hr.z + hr2.z)) * hv.z;
    rr.w = sigm(rl(xr.w + xr2.w) + rl(hr.w + hr2.w)) * hv.w;
    *(float4*)(g_z + i * 128 + q * 4) = z;
    *(float4*)(g_rh + i * 128 + q * 4) = rr;
}

__global__ void combine_h_kernel(const float* __restrict__ h, float* __restrict__ out) {
    size_t idx = (size_t)blockIdx.x * blockDim.x + threadIdx.x;
    if (idx >= (size_t)NN * 32) return;
    size_t i = idx >> 5;
    int q = (int)(idx & 31);
    float4 xh = *(const float4*)(g_bufX + i * 384 + 256 + q * 4);
    float4 xh2 = *(const float4*)(g_bufX2 + i * 384 + 256 + q * 4);
    float4 hh = *(const float4*)(g_bufHH + i * 128 + q * 4);
    float4 hh2 = *(const float4*)(g_bufHH2 + i * 128 + q * 4);
    float4 zv = *(const float4*)(g_z + i * 128 + q * 4);
    float4 hv = *(const float4*)(h + i * 128 + q * 4);
    float4 o;
    float t;
    t = tanhf(rl(xh.x + xh2.x) + rl(hh.x + hh2.x)); o.x = zv.x * hv.x + (1.f - zv.x) * t;
    t = tanhf(rl(xh.y + xh2.y) + rl(hh.y + hh2.y)); o.y = zv.y * hv.y + (1.f - zv.y) * t;
    t = tanhf(rl(xh.z + xh2.z) + rl(hh.z + hh2.z)); o.z = zv.z * hv.z + (1.f - zv.z) * t;
    t = tanhf(rl(xh.w + xh2.w) + rl(hh.w + hh2.w)); o.w = zv.w * hv.w + (1.f - zv.w) * t;
    *(float4*)(out + i * 128 + q * 4) = o;
}

// ---------------- host launch ----------------
extern "C" void kernel_launch(void* const* d_in, const int* in_sizes, int n_in,
                              void* d_out, int out_size) {
    cudaFuncSetAttribute(gemm_y_f, cudaFuncAttributeMaxDynamicSharedMemorySize, GEMM_SMEM);
    cudaFuncSetAttribute(gemm_self_f, cudaFuncAttributeMaxDynamicSharedMemorySize, GEMM_SMEM);

    // Side stream + events for fork-join graph parallelism (created once; reused).
    static cudaStream_t s1 = nullptr;
    static cudaEvent_t evF = nullptr, evA = nullptr, evB = nullptr, evC = nullptr,
                       evD = nullptr, evE = nullptr;
    if (!s1) {
        cudaStreamCreateWithFlags(&s1, cudaStreamNonBlocking);
        cudaEventCreateWithFlags(&evF, cudaEventDisableTiming);
        cudaEventCreateWithFlags(&evA, cudaEventDisableTiming);
        cudaEventCreateWithFlags(&evB, cudaEventDisableTiming);
        cudaEventCreateWithFlags(&evC, cudaEventDisableTiming);
        cudaEventCreateWithFlags(&evD, cudaEventDisableTiming);
        cudaEventCreateWithFlags(&evE, cudaEventDisableTiming);
    }

    int iEdge = 2, iH = 1;
    if (in_sizes[1] == 2 * EE) { iEdge = 1; iH = 2; }
    const float* x = (const float*)d_in[0];
    const float* h_prev = (const float*)d_in[iH];
    const int* ei = (const int*)d_in[iEdge];
    const int* role = (const int*)d_in[3];

    const float* P[27];
    for (int i = 0; i < 27 && (4 + i) < n_in; i++) P[i] = (const float*)d_in[4 + i];
    // xz: W,Wg,bg,S,b = P0..P4 | hz: P5..P8 | xr: P9..P13 | hr: P14..P17
    // xh: P18..P22 | hh: P23..P26
    float* out = (float*)d_out;

    int warpGrid = (NN * 32 + 255) / 256;

    // ---- Fork 1: CSR build (s1) || weight prep + Y GEMMs (main) ----
    cudaEventRecord(evF, 0);
    cudaStreamWaitEvent(s1, evF, 0);
    init_kernel<<<(PERM_SZ + 255) / 256, 256, 0, s1>>>();
    count_kernel<<<(ET + 255) / 256, 256, 0, s1>>>(ei, role);
    scan_kernel<<<1, 1024, 0, s1>>>();
    fill_kernel<<<(ET + 255) / 256, 256, 0, s1>>>(ei, role);
    cudaEventRecord(evA, s1);

    gates_kernel<<<6, 384>>>(P[1], P[2], P[6], P[7], P[10], P[11], P[15], P[16], P[19], P[20],
                             P[24], P[25]);
    ws_all_kernel<<<dim3(4, 3, 6), 256>>>(P[0], P[3], P[5], P[8], P[9], P[12], P[14], P[17],
                                          P[18], P[21], P[23], P[26]);
    img_kernel<<<24, 256>>>(P[0], P[5], P[9], P[14], P[18], P[23]);
    gemm_y_f<<<dim3(RB, 3), 256, GEMM_SMEM>>>(x, 0, P[4], P[13], P[22], role);
    gemm_y_f<<<dim3(RB, 2), 256, GEMM_SMEM>>>(h_prev, 1, nullptr, nullptr, nullptr, role);
    cudaStreamWaitEvent(0, evA, 0);  // join: CSR ready

    // ---- Fork 2: gathers (main, L2-bound) || self GEMMs (s1, tensor-bound) ----
    cudaEventRecord(evB, 0);
    cudaStreamWaitEvent(s1, evB, 0);
    gemm_self_f<<<dim3(SB, 3), 256, GEMM_SMEM, s1>>>(x, 0);
    gemm_self_f<<<dim3(SB, 2), 256, GEMM_SMEM, s1>>>(h_prev, 1);
    cudaEventRecord(evC, s1);
    gather_xh_kernel<<<warpGrid, 256>>>();
    cudaStreamWaitEvent(0, evC, 0);  // join

    combine_zr_kernel<<<warpGrid, 256>>>(h_prev);

    // ---- Fork 3: self_hh (s1) || yHH -> gather_hh (main) ----
    cudaEventRecord(evD, 0);
    cudaStreamWaitEvent(s1, evD, 0);
    gemm_self_f<<<dim3(SB, 1), 256, GEMM_SMEM, s1>>>(nullptr, 2);
    cudaEventRecord(evE, s1);
    gemm_y_f<<<dim3(RB, 1), 256, GEMM_SMEM>>>(nullptr, 2, nullptr, nullptr, nullptr, role);
    gather_hh_kernel<<<warpGrid, 256>>>();
    cudaStreamWaitEvent(0, evE, 0);  // join

    combine_h_kernel<<<warpGrid, 256>>>(h_prev, out);
}

// round 13
// speedup vs baseline: 2.0202x; 1.0356x over previous
#include <cuda_runtime.h>
#include <cuda_bf16.h>
#include <cstdint>

// Problem constants
#define NN 50000
#define EE 1600000
#define ET (EE + NN)
#define DHD 128
#define PERM_SZ (NN + 3 * 128)
#define RB ((NN + 127) / 128)       // 391
#define SB ((PERM_SZ + 127) / 128)  // 396

// Dynamic smem (words): A[128][68] | Bfrag chunk [8][16][64]
#define SA_STRIDE 68
#define OFF_B (128 * SA_STRIDE)
#define GEMM_SMEM ((128 * SA_STRIDE + 8 * 16 * 64) * 4)  // 67584 B

// ---------------- device scratch ----------------
__device__ __nv_bfloat16 g_yX[(size_t)NN * 384];   // gated X-side messages (xz|xr|xh)
__device__ __nv_bfloat16 g_yH[(size_t)NN * 256];   // gated h-side messages (hz|hr)
__device__ __nv_bfloat16 g_yHH[(size_t)NN * 128];  // gated rh messages (hh)
__device__ float g_bufX[(size_t)NN * 384];   // gather results
__device__ float g_bufH[(size_t)NN * 256];
__device__ float g_bufX2[(size_t)NN * 384];  // self-GEMM results (separate: enables overlap)
__device__ float g_bufH2[(size_t)NN * 256];
__device__ float g_bufHH2[(size_t)NN * 128];
__device__ float g_z[(size_t)NN * DHD];
__device__ float g_rh[(size_t)NN * DHD];
__device__ float g_WS[18 * DHD * DHD];       // per-conv per-role W@S (plain [k][n])
__device__ float g_gate[6 * 3 * DHD];        // sigmoid(Wg+bg) per conv/role
__device__ uint32_t g_Bimg[24 * DHD * DHD];  // tf32 fragment-ordered B images
__device__ int g_deg[NN];
__device__ int g_off[NN + 1];
__device__ int g_pos[NN];
__device__ int g_csr[ET];
__device__ int g_roleCnt[3];
__device__ int g_rolePadOff[4];
__device__ int g_rolePos[3];
__device__ int g_perm[PERM_SZ];

// ---------------- tf32 helpers ----------------
__device__ __forceinline__ uint32_t f2tf32(float x) {
    uint32_t r;
    asm("cvt.rna.tf32.f32 %0, %1;" : "=r"(r) : "f"(x));
    return r;
}
__device__ __forceinline__ void mma8(float* c, const uint32_t* a, uint2 b) {
    asm volatile(
        "mma.sync.aligned.m16n8k8.row.col.f32.tf32.tf32.f32 "
        "{%0,%1,%2,%3},{%4,%5,%6,%7},{%8,%9},{%0,%1,%2,%3};"
        : "+f"(c[0]), "+f"(c[1]), "+f"(c[2]), "+f"(c[3])
        : "r"(a[0]), "r"(a[1]), "r"(a[2]), "r"(a[3]), "r"(b.x), "r"(b.y));
}

// ---------------- preprocessing ----------------
__global__ void init_kernel() {
    int i = blockIdx.x * blockDim.x + threadIdx.x;
    if (i < NN) g_deg[i] = 0;
    if (i < 3) g_roleCnt[i] = 0;
    if (i < PERM_SZ) g_perm[i] = -1;
}

// 4 edges per thread (one int4 load) for MLP; REDs are fire-and-forget.
__global__ void count_kernel(const int* __restrict__ ei, const int* __restrict__ role) {
    int t = blockIdx.x * blockDim.x + threadIdx.x;
    int e4 = t * 4;
    if (e4 + 3 < EE) {
        int4 c4 = *(const int4*)(ei + EE + e4);
        atomicAdd(&g_deg[c4.x], 1);
        atomicAdd(&g_deg[c4.y], 1);
        atomicAdd(&g_deg[c4.z], 1);
        atomicAdd(&g_deg[c4.w], 1);
    } else {
        for (int e = e4; e < e4 + 4 && e < ET; e++) {
            int c = (e < EE) ? ei[EE + e] : (e - EE);
            atomicAdd(&g_deg[c], 1);
        }
    }
    int n4 = t * 4;
    if (n4 + 3 < NN) {
        int4 r4 = *(const int4*)(role + n4);
        atomicAdd(&g_roleCnt[r4.x], 1);
        atomicAdd(&g_roleCnt[r4.y], 1);
        atomicAdd(&g_roleCnt[r4.z], 1);
        atomicAdd(&g_roleCnt[r4.w], 1);
    } else {
        for (int n = n4; n < n4 + 4 && n < NN; n++) atomicAdd(&g_roleCnt[role[n]], 1);
    }
}

__global__ void scan_kernel() {
    __shared__ int warpsum[32];
    __shared__ int s_tot;
    __shared__ int s_carry;
    int t = threadIdx.x, lane = t & 31, w = t >> 5;
    if (t == 0) s_carry = 0;
    __syncthreads();
    for (int base = 0; base < NN; base += 1024) {
        int v = (base + t < NN) ? g_deg[base + t] : 0;
        int s = v;
#pragma unroll
        for (int o = 1; o < 32; o <<= 1) {
            int n = __shfl_up_sync(~0u, s, o);
            if (lane >= o) s += n;
        }
        if (lane == 31) warpsum[w] = s;
        __syncthreads();
        if (w == 0) {
            int ws = warpsum[lane];
            int t2 = ws;
#pragma unroll
            for (int o = 1; o < 32; o <<= 1) {
                int n = __shfl_up_sync(~0u, t2, o);
                if (lane >= o) t2 += n;
            }
            warpsum[lane] = t2 - ws;
            if (lane == 31) s_tot = t2;
        }
        __syncthreads();
        int excl = s_carry + warpsum[w] + s - v;
        if (base + t < NN) {
            g_off[base + t] = excl;
            g_pos[base + t] = excl;
        }
        __syncthreads();
        if (t == 0) s_carry += s_tot;
        __syncthreads();
    }
    if (t == 0) {
        g_off[NN] = s_carry;
        int o = 0;
        for (int r2 = 0; r2 < 3; r2++) {
            g_rolePadOff[r2] = o;
            g_rolePos[r2] = o;
            o += ((g_roleCnt[r2] + 127) >> 7) << 7;
        }
        g_rolePadOff[3] = o;
    }
}

// 4 edges per thread; int4 loads of rows+cols.
__global__ void fill_kernel(const int* __restrict__ ei, const int* __restrict__ role) {
    int t = blockIdx.x * blockDim.x + threadIdx.x;
    int e4 = t * 4;
    if (e4 + 3 < EE) {
        int4 r4 = *(const int4*)(ei + e4);
        int4 c4 = *(const int4*)(ei + EE + e4);
        g_csr[atomicAdd(&g_pos[c4.x], 1)] = r4.x;
        g_csr[atomicAdd(&g_pos[c4.y], 1)] = r4.y;
        g_csr[atomicAdd(&g_pos[c4.z], 1)] = r4.z;
        g_csr[atomicAdd(&g_pos[c4.w], 1)] = r4.w;
    } else {
        for (int e = e4; e < e4 + 4 && e < ET; e++) {
            int r, c;
            if (e < EE) { r = ei[e]; c = ei[EE + e]; }
            else { r = e - EE; c = e - EE; }
            g_csr[atomicAdd(&g_pos[c], 1)] = r;
        }
    }
    int n4 = t * 4;
    if (n4 + 3 < NN) {
        int4 r4 = *(const int4*)(role + n4);
        g_perm[atomicAdd(&g_rolePos[r4.x], 1)] = n4;
        g_perm[atomicAdd(&g_rolePos[r4.y], 1)] = n4 + 1;
        g_perm[atomicAdd(&g_rolePos[r4.z], 1)] = n4 + 2;
        g_perm[atomicAdd(&g_rolePos[r4.w], 1)] = n4 + 3;
    } else {
        for (int n = n4; n < n4 + 4 && n < NN; n++)
            g_perm[atomicAdd(&g_rolePos[role[n]], 1)] = n;
    }
}

// gates: sigmoid(Wg + bg) for all 6 convs (order: xz,hz,xr,hr,xh,hh)
__global__ void gates_kernel(const float* g0, const float* b0, const float* g1, const float* b1,
                             const float* g2, const float* b2, const float* g3, const float* b3,
                             const float* g4, const float* b4, const float* g5, const float* b5) {
    int c = blockIdx.x, t = threadIdx.x;
    const float* gp;
    const float* bp;
    switch (c) {
        case 0: gp = g0; bp = b0; break;
        case 1: gp = g1; bp = b1; break;
        case 2: gp = g2; bp = b2; break;
        case 3: gp = g3; bp = b3; break;
        case 4: gp = g4; bp = b4; break;
        default: gp = g5; bp = b5; break;
    }
    float v = gp[t] + bp[t];
    g_gate[c * 384 + t] = 1.0f / (1.0f + __expf(-v));
}

// ---------------- WS[conv][r] = W @ S[r] (fp32 exact, tiny) ----------------
__global__ void __launch_bounds__(256) ws_all_kernel(
    const float* W0, const float* S0, const float* W1, const float* S1,
    const float* W2, const float* S2, const float* W3, const float* S3,
    const float* W4, const float* S4, const float* W5, const float* S5) {
    int conv = blockIdx.z, r = blockIdx.y, ct = blockIdx.x;
    const float* W;
    const float* S;
    switch (conv) {
        case 0: W = W0; S = S0; break;
        case 1: W = W1; S = S1; break;
        case 2: W = W2; S = S2; break;
        case 3: W = W3; S = S3; break;
        case 4: W = W4; S = S4; break;
        default: W = W5; S = S5; break;
    }
    const float* B = S + ((size_t)r << 14) + ct * 32;
    float* C = g_WS + (((size_t)conv * 3 + r) << 14) + ct * 32;

    __shared__ float As[DHD][33];
    __shared__ float Bs[32][33];
    int tid = threadIdx.x;
    int tr = tid >> 4, tc = tid & 15;
    float acc[8][2] = {};
    for (int kc = 0; kc < DHD; kc += 32) {
#pragma unroll
        for (int t = 0; t < 4; t++) {
            int idx = tid + t * 256;
            int row = idx >> 3;
            int kq = (idx & 7) << 2;
            float4 v = *(const float4*)&W[(size_t)row * DHD + kc + kq];
            As[row][kq] = v.x; As[row][kq + 1] = v.y; As[row][kq + 2] = v.z; As[row][kq + 3] = v.w;
        }
#pragma unroll
        for (int t = 0; t < 4; t++) {
            int idx = tid + t * 256;
            int kk = idx >> 5;
            int j = idx & 31;
            Bs[kk][j] = B[(size_t)(kc + kk) * DHD + j];
        }
        __syncthreads();
#pragma unroll 8
        for (int kk = 0; kk < 32; kk++) {
            float b0 = Bs[kk][tc * 2], b1 = Bs[kk][tc * 2 + 1];
#pragma unroll
            for (int i = 0; i < 8; i++) {
                float a = As[tr * 8 + i][kk];
                acc[i][0] += a * b0;
                acc[i][1] += a * b1;
            }
        }
        __syncthreads();
    }
#pragma unroll
    for (int i = 0; i < 8; i++) {
        C[(size_t)(tr * 8 + i) * DHD + tc * 2] = acc[i][0];
        C[(size_t)(tr * 8 + i) * DHD + tc * 2 + 1] = acc[i][1];
    }
}

// ---------------- build tf32 fragment-ordered B images ----------------
__global__ void __launch_bounds__(256) img_kernel(const float* W0, const float* W1,
                                                  const float* W2, const float* W3,
                                                  const float* W4, const float* W5) {
    int m = blockIdx.x;
    const float* src;
    switch (m) {
        case 0: src = W0; break;
        case 1: src = W1; break;
        case 2: src = W2; break;
        case 3: src = W3; break;
        case 4: src = W4; break;
        case 5: src = W5; break;
        default: src = g_WS + (size_t)(m - 6) * 16384; break;
    }
    uint32_t* dst = g_Bimg + (size_t)m * 16384;
    for (int i = threadIdx.x; i < 16384; i += 256) {
        int l2 = i & 63;
        int nt = (i >> 6) & 15;
        int kit = i >> 10;
        int lane = l2 >> 1, half = l2 & 1;
        int k = kit * 8 + (lane & 3) + half * 4;
        int n = nt * 8 + (lane >> 2);
        dst[i] = f2tf32(src[k * DHD + n]);
    }
}

// ---------------- tf32 tensor-core GEMM mainloop (single-pass A) ----------------
__device__ __forceinline__ void gemm_mainloop(float (*acc)[8][4], uint32_t* sm,
                                              const float* __restrict__ Xp,
                                              const int* rows, int matIdx, int tid) {
    int lane = tid & 31, wid = tid >> 5;
    int warp_m = wid & 3, warp_n = wid >> 2;
    uint32_t* sA = sm;
    uint32_t* sB = sm + OFF_B;

    for (int kc = 0; kc < 2; kc++) {
        if (kc) __syncthreads();
#pragma unroll
        for (int it = 0; it < 8; it++) {
            int i = tid + it * 256;
            int row = i >> 4, f4 = i & 15;
            int gr = rows[row];
            float4 v = make_float4(0.f, 0.f, 0.f, 0.f);
            if (gr >= 0) v = *(const float4*)(Xp + (size_t)gr * DHD + kc * 64 + f4 * 4);
            int base = row * SA_STRIDE + f4 * 4;
            *(uint4*)(sA + base) = make_uint4(f2tf32(v.x), f2tf32(v.y), f2tf32(v.z), f2tf32(v.w));
        }
        const uint4* bsrc = (const uint4*)(g_Bimg + (size_t)matIdx * 16384 + kc * 8192);
#pragma unroll
        for (int it = 0; it < 8; it++) {
            ((uint4*)sB)[tid + it * 256] = bsrc[tid + it * 256];
        }
        __syncthreads();

#pragma unroll
        for (int kit = 0; kit < 8; kit++) {
            uint32_t ah[2][4];
#pragma unroll
            for (int mt = 0; mt < 2; mt++) {
                int r0 = warp_m * 32 + mt * 16 + (lane >> 2);
                int kk = kit * 8 + (lane & 3);
                ah[mt][0] = sA[r0 * SA_STRIDE + kk];
                ah[mt][1] = sA[(r0 + 8) * SA_STRIDE + kk];
                ah[mt][2] = sA[r0 * SA_STRIDE + kk + 4];
                ah[mt][3] = sA[(r0 + 8) * SA_STRIDE + kk + 4];
            }
#pragma unroll
            for (int nt = 0; nt < 8; nt++) {
                int gnt = warp_n * 8 + nt;
                uint2 b = *(uint2*)(sB + (kit * 16 + gnt) * 64 + lane * 2);
#pragma unroll
                for (int mt = 0; mt < 2; mt++) {
                    mma8(acc[mt][nt], ah[mt], b);
                }
            }
        }
    }
}

#define DECL_ACC(acc)                     \
    float acc[2][8][4];                   \
    _Pragma("unroll") for (int _a = 0; _a < 2; _a++) _Pragma("unroll") for (int _b = 0;        \
                                                                            _b < 8; _b++)      \
        _Pragma("unroll") for (int _c = 0; _c < 4; _c++) acc[_a][_b][_c] = 0.f;

// ---------------- fused Y GEMMs (bf16 output) ----------------
// mode 0: X -> g_yX [N,384], convs {0,2,4}, with bias
// mode 1: h -> g_yH [N,256], convs {1,3}
// mode 2: rh -> g_yHH [N,128], conv 5
__global__ void __launch_bounds__(256) gemm_y_f(const float* __restrict__ Aext, int mode,
                                                const float* __restrict__ bxz,
                                                const float* __restrict__ bxr,
                                                const float* __restrict__ bxh,
                                                const int* __restrict__ role) {
    extern __shared__ __align__(16) uint32_t sm[];
    __shared__ float sg[DHD * 3];
    __shared__ float bb[DHD * 3];
    __shared__ int role_s[DHD];
    __shared__ int rows[DHD];

    int tid = threadIdx.x, ct = blockIdx.y;
    int r0 = blockIdx.x * DHD;
    const float* Xp = Aext ? Aext : g_rh;

    int conv, ostride;
    __nv_bfloat16* obase;
    const float* bvec = nullptr;
    if (mode == 0) {
        conv = ct * 2;
        ostride = 384;
        obase = g_yX;
        bvec = (ct == 0) ? bxz : ((ct == 1) ? bxr : bxh);
    } else if (mode == 1) {
        conv = 1 + ct * 2;
        ostride = 256;
        obase = g_yH;
    } else {
        conv = 5;
        ostride = 128;
        obase = g_yHH;
    }

    for (int t = tid; t < 3 * DHD; t += 256) {
        sg[t] = g_gate[conv * 384 + t];
        bb[t] = bvec ? bvec[t] : 0.0f;
    }
    if (tid < DHD) {
        int gr = r0 + tid;
        rows[tid] = (gr < NN) ? gr : -1;
        role_s[tid] = (gr < NN) ? role[gr] : 0;
    }
    __syncthreads();

    DECL_ACC(acc)
    gemm_mainloop(acc, sm, Xp, rows, conv, tid);

    int lane = tid & 31, wid = tid >> 5;
    int warp_m = wid & 3, warp_n = wid >> 2;
#pragma unroll
    for (int mt = 0; mt < 2; mt++) {
#pragma unroll
        for (int h = 0; h < 2; h++) {
            int lrow = warp_m * 32 + mt * 16 + (lane >> 2) + h * 8;
            int grow = r0 + lrow;
            if (grow >= NN) continue;
            int rb = role_s[lrow] * 128;
            __nv_bfloat16* yp = obase + (size_t)grow * ostride + ct * 128;
#pragma unroll
            for (int nt = 0; nt < 8; nt++) {
                int col = warp_n * 64 + nt * 8 + (lane & 3) * 2;
                float v0 = acc[mt][nt][h * 2] * sg[rb + col] + bb[rb + col];
                float v1 = acc[mt][nt][h * 2 + 1] * sg[rb + col + 1] + bb[rb + col + 1];
                *(__nv_bfloat162*)(yp + col) = __float22bfloat162_rn(make_float2(v0, v1));
            }
        }
    }
}

// ---------------- fused self GEMMs: buf2 = A[node] @ WS[conv][role] (overwrite) -----
__global__ void __launch_bounds__(256) gemm_self_f(const float* __restrict__ Aext, int mode) {
    int rowBase = blockIdx.x * DHD;
    if (rowBase >= g_rolePadOff[3]) return;
    extern __shared__ __align__(16) uint32_t sm[];
    __shared__ int rows[DHD];

    int tid = threadIdx.x, ct = blockIdx.y;
    const float* Xp = Aext ? Aext : g_rh;

    int r = 0;
    if (rowBase >= g_rolePadOff[1]) r = 1;
    if (rowBase >= g_rolePadOff[2]) r = 2;

    int conv, ostride;
    float* obase;
    if (mode == 0) { conv = ct * 2; ostride = 384; obase = g_bufX2; }
    else if (mode == 1) { conv = 1 + ct * 2; ostride = 256; obase = g_bufH2; }
    else { conv = 5; ostride = 128; obase = g_bufHH2; }
    int matIdx = 6 + conv * 3 + r;

    if (tid < DHD) rows[tid] = (rowBase + tid < PERM_SZ) ? g_perm[rowBase + tid] : -1;
    __syncthreads();

    DECL_ACC(acc)
    gemm_mainloop(acc, sm, Xp, rows, matIdx, tid);

    int lane = tid & 31, wid = tid >> 5;
    int warp_m = wid & 3, warp_n = wid >> 2;
#pragma unroll
    for (int mt = 0; mt < 2; mt++) {
#pragma unroll
        for (int h = 0; h < 2; h++) {
            int lrow = warp_m * 32 + mt * 16 + (lane >> 2) + h * 8;
            int node = rows[lrow];
            if (node < 0) continue;
            float* cp = obase + (size_t)node * ostride + ct * 128;
#pragma unroll
            for (int nt = 0; nt < 8; nt++) {
                int col = warp_n * 64 + nt * 8 + (lane & 3) * 2;
                *(float2*)(cp + col) =
                    make_float2(acc[mt][nt][h * 2], acc[mt][nt][h * 2 + 1]);
            }
        }
    }
}

// ---------------- fused gathers (warp per node) ----------------
__device__ __forceinline__ void bfacc(float4& a, uint2 u) {
    float2 f0 = __bfloat1622float2(*(__nv_bfloat162*)&u.x);
    float2 f1 = __bfloat1622float2(*(__nv_bfloat162*)&u.y);
    a.x += f0.x; a.y += f0.y; a.z += f1.x; a.w += f1.y;
}
__device__ __forceinline__ float4 scale4(float4 a, float s) {
    return make_float4(a.x * s, a.y * s, a.z * s, a.w * s);
}

// combined gather over yX (3 segs) and yH (2 segs)
__global__ void __launch_bounds__(256) gather_xh_kernel() {
    int w = (blockIdx.x * blockDim.x + threadIdx.x) >> 5;
    int lane = threadIdx.x & 31;
    if (w >= NN) return;
    int s = g_off[w], e = g_off[w + 1];
    float4 a[5];
#pragma unroll
    for (int q = 0; q < 5; q++) a[q] = make_float4(0.f, 0.f, 0.f, 0.f);
    for (int p = s; p < e; p++) {
        int s0 = g_csr[p];
        const uint2* bx = (const uint2*)(g_yX + (size_t)s0 * 384);
        const uint2* bh = (const uint2*)(g_yH + (size_t)s0 * 256);
        uint2 u[5];
#pragma unroll
        for (int q = 0; q < 3; q++) u[q] = bx[lane + q * 32];
#pragma unroll
        for (int q = 0; q < 2; q++) u[3 + q] = bh[lane + q * 32];
#pragma unroll
        for (int q = 0; q < 5; q++) bfacc(a[q], u[q]);
    }
    float inv = 1.0f / (float)(e - s);
    float* ox = g_bufX + (size_t)w * 384;
    float* oh = g_bufH + (size_t)w * 256;
#pragma unroll
    for (int q = 0; q < 3; q++) *(float4*)(ox + q * 128 + lane * 4) = scale4(a[q], inv);
#pragma unroll
    for (int q = 0; q < 2; q++) *(float4*)(oh + q * 128 + lane * 4) = scale4(a[3 + q], inv);
}

// ---------------- combines ----------------
__device__ __forceinline__ float sigm(float x) { return 1.0f / (1.0f + __expf(-x)); }
__device__ __forceinline__ float rl(float x) { return fmaxf(x, 0.f); }

__global__ void combine_zr_kernel(const float* __restrict__ h) {
    size_t idx = (size_t)blockIdx.x * blockDim.x + threadIdx.x;
    if (idx >= (size_t)NN * 32) return;
    size_t i = idx >> 5;
    int q = (int)(idx & 31);
    float4 xz = *(const float4*)(g_bufX + i * 384 + q * 4);
    float4 xz2 = *(const float4*)(g_bufX2 + i * 384 + q * 4);
    float4 xr = *(const float4*)(g_bufX + i * 384 + 128 + q * 4);
    float4 xr2 = *(const float4*)(g_bufX2 + i * 384 + 128 + q * 4);
    float4 hz = *(const float4*)(g_bufH + i * 256 + q * 4);
    float4 hz2 = *(const float4*)(g_bufH2 + i * 256 + q * 4);
    float4 hr = *(const float4*)(g_bufH + i * 256 + 128 + q * 4);
    float4 hr2 = *(const float4*)(g_bufH2 + i * 256 + 128 + q * 4);
    float4 hv = *(const float4*)(h + i * 128 + q * 4);
    float4 z, rr;
    z.x = sigm(rl(xz.x + xz2.x) + rl(hz.x + hz2.x));
    z.y = sigm(rl(xz.y + xz2.y) + rl(hz.y + hz2.y));
    z.z = sigm(rl(xz.z + xz2.z) + rl(hz.z + hz2.z));
    z.w = sigm(rl(xz.w + xz2.w) + rl(hz.w + hz2.w));
    rr.x = sigm(rl(xr.x + xr2.x) + rl(hr.x + hr2.x)) * hv.x;
    rr.y = sigm(rl(xr.y + xr2.y) + rl(hr.y + hr2.y)) * hv.y;
    rr.z = sigm(rl(xr.z + xr2.z) + rl(hr.z + hr2.z)) * hv.z;
    rr.w = sigm(rl(xr.w + xr2.w) + rl(hr.w + hr2.w)) * hv.w;
    *(float4*)(g_z + i * 128 + q * 4) = z;
    *(float4*)(g_rh + i * 128 + q * 4) = rr;
}

// fused: gather yHH (mean) + final GRU combine, writes out directly.
// Requires self_hh (g_bufHH2) complete before launch.
__global__ void __launch_bounds__(256) gather_hh_combine_kernel(const float* __restrict__ h,
                                                                float* __restrict__ out) {
    int w = (blockIdx.x * blockDim.x + threadIdx.x) >> 5;
    int lane = threadIdx.x & 31;
    if (w >= NN) return;
    int s = g_off[w], e = g_off[w + 1];
    float4 a0 = make_float4(0.f, 0.f, 0.f, 0.f);
    float4 a1 = make_float4(0.f, 0.f, 0.f, 0.f);
    int p = s;
    for (; p + 2 <= e; p += 2) {
        int s0 = g_csr[p], s1 = g_csr[p + 1];
        uint2 u0 = ((const uint2*)(g_yHH + (size_t)s0 * 128))[lane];
        uint2 u1 = ((const uint2*)(g_yHH + (size_t)s1 * 128))[lane];
        bfacc(a0, u0);
        bfacc(a1, u1);
    }
    if (p < e) {
        uint2 u0 = ((const uint2*)(g_yHH + (size_t)g_csr[p] * 128))[lane];
        bfacc(a0, u0);
    }
    float inv = 1.0f / (float)(e - s);
    a0.x += a1.x; a0.y += a1.y; a0.z += a1.z; a0.w += a1.w;
    float4 hh = scale4(a0, inv);  // gathered mean

    size_t base = (size_t)w * 128 + lane * 4;
    float4 hh2 = *(const float4*)(g_bufHH2 + base);
    float4 xh = *(const float4*)(g_bufX + (size_t)w * 384 + 256 + lane * 4);
    float4 xh2 = *(const float4*)(g_bufX2 + (size_t)w * 384 + 256 + lane * 4);
    float4 zv = *(const float4*)(g_z + base);
    float4 hv = *(const float4*)(h + base);
    float4 o;
    float t;
    t = tanhf(rl(xh.x + xh2.x) + rl(hh.x + hh2.x)); o.x = zv.x * hv.x + (1.f - zv.x) * t;
    t = tanhf(rl(xh.y + xh2.y) + rl(hh.y + hh2.y)); o.y = zv.y * hv.y + (1.f - zv.y) * t;
    t = tanhf(rl(xh.z + xh2.z) + rl(hh.z + hh2.z)); o.z = zv.z * hv.z + (1.f - zv.z) * t;
    t = tanhf(rl(xh.w + xh2.w) + rl(hh.w + hh2.w)); o.w = zv.w * hv.w + (1.f - zv.w) * t;
    *(float4*)(out + base) = o;
}

// ---------------- host launch ----------------
extern "C" void kernel_launch(void* const* d_in, const int* in_sizes, int n_in,
                              void* d_out, int out_size) {
    cudaFuncSetAttribute(gemm_y_f, cudaFuncAttributeMaxDynamicSharedMemorySize, GEMM_SMEM);
    cudaFuncSetAttribute(gemm_self_f, cudaFuncAttributeMaxDynamicSharedMemorySize, GEMM_SMEM);

    // Side stream + events for fork-join graph parallelism (created once; reused).
    static cudaStream_t s1 = nullptr;
    static cudaEvent_t evF = nullptr, evA = nullptr, evB = nullptr, evC = nullptr,
                       evD = nullptr, evE = nullptr;
    if (!s1) {
        cudaStreamCreateWithFlags(&s1, cudaStreamNonBlocking);
        cudaEventCreateWithFlags(&evF, cudaEventDisableTiming);
        cudaEventCreateWithFlags(&evA, cudaEventDisableTiming);
        cudaEventCreateWithFlags(&evB, cudaEventDisableTiming);
        cudaEventCreateWithFlags(&evC, cudaEventDisableTiming);
        cudaEventCreateWithFlags(&evD, cudaEventDisableTiming);
        cudaEventCreateWithFlags(&evE, cudaEventDisableTiming);
    }

    int iEdge = 2, iH = 1;
    if (in_sizes[1] == 2 * EE) { iEdge = 1; iH = 2; }
    const float* x = (const float*)d_in[0];
    const float* h_prev = (const float*)d_in[iH];
    const int* ei = (const int*)d_in[iEdge];
    const int* role = (const int*)d_in[3];

    const float* P[27];
    for (int i = 0; i < 27 && (4 + i) < n_in; i++) P[i] = (const float*)d_in[4 + i];
    // xz: W,Wg,bg,S,b = P0..P4 | hz: P5..P8 | xr: P9..P13 | hr: P14..P17
    // xh: P18..P22 | hh: P23..P26
    float* out = (float*)d_out;

    int warpGrid = (NN * 32 + 255) / 256;
    int e4Grid = (ET / 4 + 256) / 256 + 1;

    // ---- Fork 1: CSR build (s1) || weight prep + Y GEMMs (main) ----
    cudaEventRecord(evF, 0);
    cudaStreamWaitEvent(s1, evF, 0);
    init_kernel<<<(PERM_SZ + 255) / 256, 256, 0, s1>>>();
    count_kernel<<<e4Grid, 256, 0, s1>>>(ei, role);
    scan_kernel<<<1, 1024, 0, s1>>>();
    fill_kernel<<<e4Grid, 256, 0, s1>>>(ei, role);
    cudaEventRecord(evA, s1);

    gates_kernel<<<6, 384>>>(P[1], P[2], P[6], P[7], P[10], P[11], P[15], P[16], P[19], P[20],
                             P[24], P[25]);
    ws_all_kernel<<<dim3(4, 3, 6), 256>>>(P[0], P[3], P[5], P[8], P[9], P[12], P[14], P[17],
                                          P[18], P[21], P[23], P[26]);
    img_kernel<<<24, 256>>>(P[0], P[5], P[9], P[14], P[18], P[23]);
    gemm_y_f<<<dim3(RB, 3), 256, GEMM_SMEM>>>(x, 0, P[4], P[13], P[22], role);
    gemm_y_f<<<dim3(RB, 2), 256, GEMM_SMEM>>>(h_prev, 1, nullptr, nullptr, nullptr, role);
    cudaStreamWaitEvent(0, evA, 0);  // join: CSR ready

    // ---- Fork 2: gathers (main, L2-bound) || self GEMMs (s1, tensor-bound) ----
    cudaEventRecord(evB, 0);
    cudaStreamWaitEvent(s1, evB, 0);
    gemm_self_f<<<dim3(SB, 3), 256, GEMM_SMEM, s1>>>(x, 0);
    gemm_self_f<<<dim3(SB, 2), 256, GEMM_SMEM, s1>>>(h_prev, 1);
    cudaEventRecord(evC, s1);
    gather_xh_kernel<<<warpGrid, 256>>>();
    cudaStreamWaitEvent(0, evC, 0);  // join

    combine_zr_kernel<<<warpGrid, 256>>>(h_prev);

    // ---- Fork 3: self_hh (s1) || yHH GEMM (main); join; fused gather+combine ----
    cudaEventRecord(evD, 0);
    cudaStreamWaitEvent(s1, evD, 0);
    gemm_self_f<<<dim3(SB, 1), 256, GEMM_SMEM, s1>>>(nullptr, 2);
    cudaEventRecord(evE, s1);
    gemm_y_f<<<dim3(RB, 1), 256, GEMM_SMEM>>>(nullptr, 2, nullptr, nullptr, nullptr, role);
    cudaStreamWaitEvent(0, evE, 0);  // join: self_hh done
    gather_hh_combine_kernel<<<warpGrid, 256>>>(h_prev, out);
}